// round 4
// baseline (speedup 1.0000x reference)
#include <cuda_runtime.h>
#include <cuda_bf16.h>
#include <mma.h>
#include <math.h>

using namespace nvcuda;

// Problem constants (fixed shapes for this problem instance)
#define NN 50000
#define EE 800000
#define HH 4
#define FF 64
#define CC 256   // H*F == CIN
#define CAP 128  // max cached degree per node (smem path); fallback to global

// ---------------- device scratch (static, no allocation) ----------------
__device__ float    g_xcomb [(size_t)NN*CC];
__device__ float    g_xl    [(size_t)NN*CC];
__device__ float    g_xr    [(size_t)NN*CC];
__device__ float    g_ident [(size_t)NN*CC];
__device__ float    g_pre   [(size_t)NN*CC];
__device__ float    g_logits[(size_t)EE*HH];   // fallback logits cache (CSR-slot indexed)
__device__ float    g_nuv   [(size_t)NN*2];
__device__ int      g_deg   [NN+1];
__device__ int      g_off   [NN+1];
__device__ int      g_cursor[NN+1];
__device__ int      g_csr   [EE];

// ---------------- helpers ----------------
__device__ __forceinline__ float wsum(float v){
#pragma unroll
    for (int o=16;o>0;o>>=1) v += __shfl_xor_sync(0xffffffffu, v, o);
    return v;
}

__device__ __forceinline__ float blockSum256(float v){
    __shared__ float sh[8];
    float s = v;
#pragma unroll
    for (int o=16;o>0;o>>=1) s += __shfl_xor_sync(0xffffffffu, s, o);
    if ((threadIdx.x & 31) == 0) sh[threadIdx.x >> 5] = s;
    __syncthreads();
    float t = sh[0]+sh[1]+sh[2]+sh[3]+sh[4]+sh[5]+sh[6]+sh[7];
    __syncthreads();
    return t;
}

// ---------------- kernels ----------------
__global__ void k_init(){
    int i = blockIdx.x*blockDim.x + threadIdx.x;
    int stride = gridDim.x*blockDim.x;
    for (int j=i; j<NN+1; j+=stride){ g_deg[j]=0; }
}

// positional encoder + build x_comb. One warp per node.
__global__ void k_pos(const float* __restrict__ x, const float* __restrict__ kpts,
                      const float* __restrict__ pts,
                      const float* __restrict__ w1, const float* __restrict__ b1,
                      const float* __restrict__ g1, const float* __restrict__ bn1,
                      const float* __restrict__ w2, const float* __restrict__ b2,
                      const float* __restrict__ g2, const float* __restrict__ bn2)
{
    int node = (blockIdx.x*blockDim.x + threadIdx.x) >> 5;
    int lane = threadIdx.x & 31;
    if (node >= NN) return;
    float u  = kpts[node*2+0] * (1.f/1216.f);
    float v  = kpts[node*2+1] * (1.f/352.f);
    float dep = fminf(fmaxf(pts[node*3+2], 0.1f), 100.f);
    if (lane == 0){ g_nuv[node*2]=u; g_nuv[node*2+1]=v; }

    // layer 1: 3 -> 32, LN, SiLU
    float a = w1[lane*3+0]*u + w1[lane*3+1]*v + w1[lane*3+2]*dep + b1[lane];
    float m = wsum(a) * (1.f/32.f);
    float d0 = a - m;
    float var = wsum(d0*d0) * (1.f/32.f);
    float hn = d0 * rsqrtf(var + 1e-5f) * g1[lane] + bn1[lane];
    float h = hn / (1.f + expf(-hn));

    // layer 2: 32 -> 64, LN
    float acc0 = b2[lane], acc1 = b2[lane+32];
#pragma unroll
    for (int k=0;k<32;k++){
        float hk = __shfl_sync(0xffffffffu, h, k);
        acc0 += hk * w2[lane*32 + k];
        acc1 += hk * w2[(lane+32)*32 + k];
    }
    float m2 = wsum(acc0 + acc1) * (1.f/64.f);
    float e0 = acc0 - m2, e1 = acc1 - m2;
    float var2 = wsum(e0*e0 + e1*e1) * (1.f/64.f);
    float rs = rsqrtf(var2 + 1e-5f);
    float p0 = e0*rs*g2[lane]    + bn2[lane];
    float p1 = e1*rs*g2[lane+32] + bn2[lane+32];

    size_t base = (size_t)node * CC;
    g_xcomb[base + 192 + lane] = p0;
    g_xcomb[base + 224 + lane] = p1;
#pragma unroll
    for (int j=lane; j<192; j+=32) g_xcomb[base + j] = x[(size_t)node*192 + j];
}

// ---------------- tf32 tensor-core GEMM ----------------
// C[m][c] = sum_k A[m][k] * W[c][k] + bias[c]
__global__ void k_tcgemm(const float* __restrict__ A,
                         const float* __restrict__ W0, const float* __restrict__ W1,
                         const float* __restrict__ W2,
                         const float* __restrict__ b0, const float* __restrict__ b1,
                         const float* __restrict__ b2,
                         float* __restrict__ C0, float* __restrict__ C1,
                         float* __restrict__ C2, int M)
{
    __shared__ float As[64][36];
    __shared__ float Ws[64][36];
    __shared__ float Cs[64][64];

    int t = threadIdx.x;
    int m0 = blockIdx.x * 64;
    int tgt = blockIdx.y >> 2;
    int c0l = (blockIdx.y & 3) * 64;

    const float* W    = (tgt == 0) ? W0 : (tgt == 1) ? W1 : W2;
    const float* bias = (tgt == 0) ? b0 : (tgt == 1) ? b1 : b2;
    float*       C    = (tgt == 0) ? C0 : (tgt == 1) ? C1 : C2;

    int warp = t >> 5;
    int r  = (warp >> 1) * 16;
    int cb = (warp & 1) * 32;

    wmma::fragment<wmma::accumulator, 16, 16, 8, float> acc0f, acc1f;
    wmma::fill_fragment(acc0f, 0.f);
    wmma::fill_fragment(acc1f, 0.f);

    for (int k0 = 0; k0 < CC; k0 += 32){
#pragma unroll
        for (int j = 0; j < 2; j++){
            int id  = t + j * 256;
            int row = id >> 3;
            int col = (id & 7) * 4;
            float4 av = make_float4(0.f,0.f,0.f,0.f);
            if (m0 + row < M)
                av = *(const float4*)&A[(size_t)(m0 + row) * CC + k0 + col];
            *(float4*)&As[row][col] = av;
            float4 wv = *(const float4*)&W[(size_t)(c0l + row) * CC + k0 + col];
            *(float4*)&Ws[row][col] = wv;
        }
        __syncthreads();

#pragma unroll
        for (int kk = 0; kk < 32; kk += 8){
            wmma::fragment<wmma::matrix_a, 16, 16, 8, wmma::precision::tf32, wmma::row_major> af;
            wmma::fragment<wmma::matrix_b, 16, 16, 8, wmma::precision::tf32, wmma::col_major> bf0, bf1;
            wmma::load_matrix_sync(af, &As[r][kk], 36);
#pragma unroll
            for (int i = 0; i < af.num_elements; i++) af.x[i] = wmma::__float_to_tf32(af.x[i]);
            wmma::load_matrix_sync(bf0, &Ws[cb][kk], 36);
            wmma::load_matrix_sync(bf1, &Ws[cb + 16][kk], 36);
#pragma unroll
            for (int i = 0; i < bf0.num_elements; i++){
                bf0.x[i] = wmma::__float_to_tf32(bf0.x[i]);
                bf1.x[i] = wmma::__float_to_tf32(bf1.x[i]);
            }
            wmma::mma_sync(acc0f, af, bf0, acc0f);
            wmma::mma_sync(acc1f, af, bf1, acc1f);
        }
        __syncthreads();
    }

    wmma::store_matrix_sync(&Cs[r][cb],      acc0f, 64, wmma::mem_row_major);
    wmma::store_matrix_sync(&Cs[r][cb + 16], acc1f, 64, wmma::mem_row_major);
    __syncthreads();

    int ct = t & 63;
    int r0 = t >> 6;
    float bv = bias[c0l + ct];
#pragma unroll
    for (int i = 0; i < 16; i++){
        int row = r0 + i * 4;
        int m = m0 + row;
        if (m < M)
            C[(size_t)m * CC + c0l + ct] = Cs[row][ct] + bv;
    }
}

// edge_attr output + degree histogram
__global__ void k_edgeattr(const int* __restrict__ ei, float* __restrict__ ea)
{
    int e = blockIdx.x*blockDim.x + threadIdx.x;
    if (e >= EE) return;
    int s = ei[e], d = ei[EE + e];
    float r0 = g_nuv[d*2+0] - g_nuv[s*2+0];
    float r1 = g_nuv[d*2+1] - g_nuv[s*2+1];
    float dist = sqrtf(r0*r0 + r1*r1);
    ea[(size_t)e*3+0] = r0;
    ea[(size_t)e*3+1] = r1;
    ea[(size_t)e*3+2] = dist;
    atomicAdd(&g_deg[d], 1);
}

// single-block exclusive scan of degrees -> offsets (+cursor copy), warp-shuffle based
__global__ void k_scan()
{
    __shared__ int warpsum[32];
    __shared__ int warpoff[32];
    int t = threadIdx.x;
    int lane = t & 31, wid = t >> 5;
    int carry = 0;
    for (int base = 0; base < NN; base += 1024){
        int v = (base + t < NN) ? g_deg[base + t] : 0;
        int s = v;
#pragma unroll
        for (int o = 1; o < 32; o <<= 1){
            int n = __shfl_up_sync(0xffffffffu, s, o);
            if (lane >= o) s += n;
        }
        if (lane == 31) warpsum[wid] = s;
        __syncthreads();
        if (wid == 0){
            int ws = warpsum[lane];
            int t2 = ws;
#pragma unroll
            for (int o = 1; o < 32; o <<= 1){
                int n = __shfl_up_sync(0xffffffffu, t2, o);
                if (lane >= o) t2 += n;
            }
            warpoff[lane] = t2 - ws;
            if (lane == 31) warpsum[0] = t2;
        }
        __syncthreads();
        int tile_total = warpsum[0];
        if (base + t < NN){
            int ex = carry + warpoff[wid] + s - v;
            g_off[base + t] = ex;
            g_cursor[base + t] = ex;
        }
        __syncthreads();
        carry += tile_total;
    }
    if (t == 0) g_off[NN] = carry;
}

__global__ void k_scatter(const int* __restrict__ ei)
{
    int e = blockIdx.x*blockDim.x + threadIdx.x;
    if (e >= EE) return;
    int d = ei[EE + e];
    int pos = atomicAdd(&g_cursor[d], 1);
    g_csr[pos] = e;
}

// ---------------- fully fused per-destination attention ----------------
// One block (256 threads) per dst node:
//   pass 1: logits per edge (block reduce per head), running max (no atomics)
//   pass 2: softmax sums, alpha -> smem cache + alpha_out
//   pass 3: weighted aggregation + LN + residual + SiLU -> g_pre
__global__ void k_node(const int* __restrict__ ei, const float* __restrict__ ea,
                       const float* __restrict__ lew, const float* __restrict__ att,
                       const float* __restrict__ convb, const float* __restrict__ ng,
                       const float* __restrict__ nb, float* __restrict__ alpha_out)
{
    __shared__ float s_lew[768];
    __shared__ float s_att[256];
    __shared__ float s_cache[CAP*HH];
    __shared__ float s_wpart[8];
    __shared__ float s_max[HH];
    __shared__ float s_sum[HH];

    int n = blockIdx.x;
    int c = threadIdx.x;
    int h = c >> 6;
    int lane = c & 31, wid = c >> 5;

    s_att[c] = att[c];
    s_lew[c] = lew[c]; s_lew[c+256] = lew[c+256]; s_lew[c+512] = lew[c+512];
    if (c < HH) s_max[c] = -INFINITY;

    int st = g_off[n], en = g_off[n+1];
    int deg = en - st;
    float* cache = (deg <= CAP) ? s_cache : (g_logits + (size_t)st*HH);

    float xr = g_xr[(size_t)n*CC + c];
    __syncthreads();

    float wa = s_att[c];
    float l0 = s_lew[c*3+0], l1 = s_lew[c*3+1], l2 = s_lew[c*3+2];

    // ---- pass 1: logits + max ----
    for (int i = 0; i < deg; i++){
        int e = g_csr[st + i];
        int s = ei[e];
        float r0 = ea[(size_t)e*3+0];
        float r1 = ea[(size_t)e*3+1];
        float dd = ea[(size_t)e*3+2];
        float z = g_xl[(size_t)s*CC + c] + xr + r0*l0 + r1*l1 + dd*l2;
        z = (z > 0.f) ? z : 0.2f*z;
        float p = z * wa;
        p = wsum(p);                         // 32-channel partial (one head per warp)
        if (lane == 0) s_wpart[wid] = p;
        __syncthreads();
        if (c < HH){
            float lh = s_wpart[2*c] + s_wpart[2*c+1];
            cache[i*HH + c] = lh;
            s_max[c] = fmaxf(s_max[c], lh);
        }
        __syncthreads();
    }

    // ---- pass 2: softmax sums + alpha ----
    if (c < HH){
        float m = s_max[c], sum = 0.f;
        for (int i = 0; i < deg; i++) sum += expf(cache[i*HH + c] - m);
        s_sum[c] = sum;
    }
    __syncthreads();
    for (int idx = c; idx < deg*HH; idx += 256){
        int i = idx >> 2, hh = idx & 3;
        float al = expf(cache[idx] - s_max[hh]) / (s_sum[hh] + 1e-16f);
        cache[idx] = al;
        int e = g_csr[st + i];
        alpha_out[(size_t)e*HH + hh] = al;
    }
    __syncthreads();

    // ---- pass 3: aggregation + LN + residual + SiLU ----
    float acc = 0.f;
    for (int i = 0; i < deg; i++){
        int e = g_csr[st + i];
        int s = ei[e];
        acc += cache[i*HH + h] * g_xl[(size_t)s*CC + c];
    }
    float v = acc + convb[c];
    float mean = blockSum256(v) * (1.f/256.f);
    float dv = v - mean;
    float var = blockSum256(dv*dv) * (1.f/256.f);
    float o = dv * rsqrtf(var + 1e-5f) * ng[c] + nb[c];
    float tt = o + g_ident[(size_t)n*CC + c];
    g_pre[(size_t)n*CC + c] = tt / (1.f + expf(-tt));
}

// ---------------- launch ----------------
extern "C" void kernel_launch(void* const* d_in, const int* in_sizes, int n_in,
                              void* d_out, int out_size)
{
    const float* x        = (const float*)d_in[0];
    const float* kpts     = (const float*)d_in[1];
    const float* pts3d    = (const float*)d_in[2];
    const float* pe_w1    = (const float*)d_in[3];
    const float* pe_b1    = (const float*)d_in[4];
    const float* pe_g1    = (const float*)d_in[5];
    const float* pe_bn1   = (const float*)d_in[6];
    const float* pe_w2    = (const float*)d_in[7];
    const float* pe_b2    = (const float*)d_in[8];
    const float* pe_g2    = (const float*)d_in[9];
    const float* pe_bn2   = (const float*)d_in[10];
    const float* lin_l_w  = (const float*)d_in[11];
    const float* lin_l_b  = (const float*)d_in[12];
    const float* lin_r_w  = (const float*)d_in[13];
    const float* lin_r_b  = (const float*)d_in[14];
    const float* lin_edge = (const float*)d_in[15];
    const float* att      = (const float*)d_in[16];
    const float* conv_b   = (const float*)d_in[17];
    const float* norm_g   = (const float*)d_in[18];
    const float* norm_b   = (const float*)d_in[19];
    const float* res_w    = (const float*)d_in[20];
    const float* res_b    = (const float*)d_in[21];
    const float* proj_w   = (const float*)d_in[22];
    const float* proj_b   = (const float*)d_in[23];
    const int*   ei       = (const int*)d_in[24];

    float* out       = (float*)d_out;
    float* alpha_out = out + (size_t)NN*CC;          // [E,4]
    float* ea_out    = alpha_out + (size_t)EE*HH;    // [E,3]

    float *p_xcomb, *p_pre;
    cudaGetSymbolAddress((void**)&p_xcomb, g_xcomb);
    cudaGetSymbolAddress((void**)&p_pre,   g_pre);
    float *p_xl, *p_xr, *p_ident;
    cudaGetSymbolAddress((void**)&p_xl,    g_xl);
    cudaGetSymbolAddress((void**)&p_xr,    g_xr);
    cudaGetSymbolAddress((void**)&p_ident, g_ident);

    k_init<<<64, 256>>>();
    k_pos<<<(NN + 7)/8, 256>>>(x, kpts, pts3d,
                               pe_w1, pe_b1, pe_g1, pe_bn1,
                               pe_w2, pe_b2, pe_g2, pe_bn2);

    // fused lin_l + lin_r + res GEMMs (tf32 tensor cores)
    dim3 g3((NN + 63)/64, 12);
    k_tcgemm<<<g3, 256>>>(p_xcomb, lin_l_w, lin_r_w, res_w,
                          lin_l_b, lin_r_b, res_b,
                          p_xl, p_xr, p_ident, NN);

    k_edgeattr<<<(EE + 255)/256, 256>>>(ei, ea_out);
    k_scan<<<1, 1024>>>();
    k_scatter<<<(EE + 255)/256, 256>>>(ei);

    // fused attention: logits + softmax + alpha + aggregation + LN + SiLU
    k_node<<<NN, 256>>>(ei, ea_out, lin_edge, att, conv_b, norm_g, norm_b, alpha_out);

    // projector GEMM
    dim3 g1((NN + 63)/64, 4);
    k_tcgemm<<<g1, 256>>>(p_pre, proj_w, proj_w, proj_w,
                          proj_b, proj_b, proj_b,
                          out, out, out, NN);
}

// round 5
// speedup vs baseline: 1.2123x; 1.2123x over previous
#include <cuda_runtime.h>
#include <cuda_bf16.h>
#include <mma.h>
#include <math.h>

using namespace nvcuda;

// Problem constants (fixed shapes for this problem instance)
#define NN 50000
#define EE 800000
#define HH 4
#define FF 64
#define CC 256   // H*F == CIN

// ---------------- device scratch (static, no allocation) ----------------
__device__ float    g_xcomb [(size_t)NN*CC];
__device__ float    g_xl    [(size_t)NN*CC];
__device__ float    g_xr    [(size_t)NN*CC];
__device__ float    g_ident [(size_t)NN*CC];
__device__ float    g_pre   [(size_t)NN*CC];
__device__ float    g_logits[(size_t)EE*HH];
__device__ float    g_nuv   [(size_t)NN*2];
__device__ unsigned g_maxenc[(size_t)NN*HH];
__device__ float    g_sum   [(size_t)NN*HH];
__device__ int      g_deg   [NN+1];
__device__ int      g_off   [NN+1];
__device__ int      g_cursor[NN+1];
__device__ int      g_csr   [EE];

// ---------------- helpers ----------------
__device__ __forceinline__ float wsum(float v){
#pragma unroll
    for (int o=16;o>0;o>>=1) v += __shfl_xor_sync(0xffffffffu, v, o);
    return v;
}

__device__ __forceinline__ unsigned encf(float f){
    int b = __float_as_int(f);
    return (b >= 0) ? ((unsigned)b | 0x80000000u) : (unsigned)(~b);
}
__device__ __forceinline__ float decf(unsigned u){
    int b = (u & 0x80000000u) ? (int)(u & 0x7fffffffu) : (int)(~u);
    return __int_as_float(b);
}

__device__ __forceinline__ float blockSum256(float v){
    __shared__ float sh[8];
    float s = v;
#pragma unroll
    for (int o=16;o>0;o>>=1) s += __shfl_xor_sync(0xffffffffu, s, o);
    if ((threadIdx.x & 31) == 0) sh[threadIdx.x >> 5] = s;
    __syncthreads();
    float t = sh[0]+sh[1]+sh[2]+sh[3]+sh[4]+sh[5]+sh[6]+sh[7];
    __syncthreads();
    return t;
}

// ---------------- kernels ----------------
__global__ void k_init(){
    int i = blockIdx.x*blockDim.x + threadIdx.x;
    int stride = gridDim.x*blockDim.x;
    for (int j=i; j<NN*HH; j+=stride){ g_maxenc[j]=0u; g_sum[j]=0.f; }
    for (int j=i; j<NN+1;  j+=stride){ g_deg[j]=0; }
}

// positional encoder + build x_comb. One warp per node.
__global__ void k_pos(const float* __restrict__ x, const float* __restrict__ kpts,
                      const float* __restrict__ pts,
                      const float* __restrict__ w1, const float* __restrict__ b1,
                      const float* __restrict__ g1, const float* __restrict__ bn1,
                      const float* __restrict__ w2, const float* __restrict__ b2,
                      const float* __restrict__ g2, const float* __restrict__ bn2)
{
    int node = (blockIdx.x*blockDim.x + threadIdx.x) >> 5;
    int lane = threadIdx.x & 31;
    if (node >= NN) return;
    float u  = kpts[node*2+0] * (1.f/1216.f);
    float v  = kpts[node*2+1] * (1.f/352.f);
    float dep = fminf(fmaxf(pts[node*3+2], 0.1f), 100.f);
    if (lane == 0){ g_nuv[node*2]=u; g_nuv[node*2+1]=v; }

    float a = w1[lane*3+0]*u + w1[lane*3+1]*v + w1[lane*3+2]*dep + b1[lane];
    float m = wsum(a) * (1.f/32.f);
    float d0 = a - m;
    float var = wsum(d0*d0) * (1.f/32.f);
    float hn = d0 * rsqrtf(var + 1e-5f) * g1[lane] + bn1[lane];
    float h = hn / (1.f + expf(-hn));

    float acc0 = b2[lane], acc1 = b2[lane+32];
#pragma unroll
    for (int k=0;k<32;k++){
        float hk = __shfl_sync(0xffffffffu, h, k);
        acc0 += hk * w2[lane*32 + k];
        acc1 += hk * w2[(lane+32)*32 + k];
    }
    float m2 = wsum(acc0 + acc1) * (1.f/64.f);
    float e0 = acc0 - m2, e1 = acc1 - m2;
    float var2 = wsum(e0*e0 + e1*e1) * (1.f/64.f);
    float rs = rsqrtf(var2 + 1e-5f);
    float p0 = e0*rs*g2[lane]    + bn2[lane];
    float p1 = e1*rs*g2[lane+32] + bn2[lane+32];

    size_t base = (size_t)node * CC;
    g_xcomb[base + 192 + lane] = p0;
    g_xcomb[base + 224 + lane] = p1;
#pragma unroll
    for (int j=lane; j<192; j+=32) g_xcomb[base + j] = x[(size_t)node*192 + j];
}

// ---------------- tf32 tensor-core GEMM, 128x128 block tile ----------------
// C[m][c] = sum_k A[m][k]*W[c][k] + bias[c]; K=256, width per target = 256.
// blockIdx.y: tgt = y>>1, column half = (y&1)*128. 256 threads, 8 warps,
// each warp computes 32x64 (2x4 wmma 16x16x8 tf32 fragments).
// Dynamic smem: As[128][36] + Ws[128][36] during mainloop, aliased by
// Cs[128][136] in the epilogue (70KB).
__global__ void k_tcgemm2(const float* __restrict__ A,
                          const float* __restrict__ W0, const float* __restrict__ W1,
                          const float* __restrict__ W2,
                          const float* __restrict__ b0, const float* __restrict__ b1,
                          const float* __restrict__ b2,
                          float* __restrict__ C0, float* __restrict__ C1,
                          float* __restrict__ C2, int M)
{
    extern __shared__ float sm[];
    float* As = sm;             // [128][36]
    float* Ws = sm + 128*36;    // [128][36]

    int t  = threadIdx.x;
    int m0 = blockIdx.x * 128;
    int tgt = blockIdx.y >> 1;
    int c0  = (blockIdx.y & 1) * 128;

    const float* W    = (tgt == 0) ? W0 : (tgt == 1) ? W1 : W2;
    const float* bias = (tgt == 0) ? b0 : (tgt == 1) ? b1 : b2;
    float*       C    = (tgt == 0) ? C0 : (tgt == 1) ? C1 : C2;

    int warp = t >> 5;
    int r  = (warp & 3) * 32;     // warp row origin: 0,32,64,96
    int cb = (warp >> 2) * 64;    // warp col origin: 0,64

    wmma::fragment<wmma::accumulator, 16, 16, 8, float> acc[2][4];
#pragma unroll
    for (int i=0;i<2;i++)
#pragma unroll
        for (int j=0;j<4;j++) wmma::fill_fragment(acc[i][j], 0.f);

    for (int k0 = 0; k0 < CC; k0 += 32){
#pragma unroll
        for (int j = 0; j < 4; j++){
            int id  = t + j * 256;       // 0..1023
            int row = id >> 3;           // 0..127
            int col = (id & 7) * 4;      // 0..28
            float4 av = make_float4(0.f,0.f,0.f,0.f);
            if (m0 + row < M)
                av = *(const float4*)&A[(size_t)(m0 + row) * CC + k0 + col];
            *(float4*)&As[row*36 + col] = av;
            float4 wv = *(const float4*)&W[(size_t)(c0 + row) * CC + k0 + col];
            *(float4*)&Ws[row*36 + col] = wv;
        }
        __syncthreads();

#pragma unroll
        for (int kk = 0; kk < 32; kk += 8){
            wmma::fragment<wmma::matrix_a, 16, 16, 8, wmma::precision::tf32, wmma::row_major> af[2];
            wmma::fragment<wmma::matrix_b, 16, 16, 8, wmma::precision::tf32, wmma::col_major> bf[4];
#pragma unroll
            for (int i = 0; i < 2; i++){
                wmma::load_matrix_sync(af[i], &As[(r + 16*i)*36 + kk], 36);
#pragma unroll
                for (int q = 0; q < af[i].num_elements; q++)
                    af[i].x[q] = wmma::__float_to_tf32(af[i].x[q]);
            }
#pragma unroll
            for (int j = 0; j < 4; j++){
                wmma::load_matrix_sync(bf[j], &Ws[(cb + 16*j)*36 + kk], 36);
#pragma unroll
                for (int q = 0; q < bf[j].num_elements; q++)
                    bf[j].x[q] = wmma::__float_to_tf32(bf[j].x[q]);
            }
#pragma unroll
            for (int i = 0; i < 2; i++)
#pragma unroll
                for (int j = 0; j < 4; j++)
                    wmma::mma_sync(acc[i][j], af[i], bf[j], acc[i][j]);
        }
        __syncthreads();
    }

    // epilogue through smem (aliases As/Ws; safe after the loop's last sync)
    float* Cs = sm;  // [128][136]
#pragma unroll
    for (int i = 0; i < 2; i++)
#pragma unroll
        for (int j = 0; j < 4; j++)
            wmma::store_matrix_sync(&Cs[(r + 16*i)*136 + cb + 16*j], acc[i][j], 136, wmma::mem_row_major);
    __syncthreads();

    int col4 = (t & 31) * 4;
    int rb   = t >> 5;
    float4 bv = *(const float4*)&bias[c0 + col4];
#pragma unroll
    for (int i = 0; i < 16; i++){
        int row = rb + i * 8;
        int m = m0 + row;
        if (m < M){
            float4 v = *(float4*)&Cs[row*136 + col4];
            v.x += bv.x; v.y += bv.y; v.z += bv.z; v.w += bv.w;
            *(float4*)&C[(size_t)m * CC + c0 + col4] = v;
        }
    }
}

// edge_attr output + degree histogram
__global__ void k_edgeattr(const int* __restrict__ ei, float* __restrict__ ea)
{
    int e = blockIdx.x*blockDim.x + threadIdx.x;
    if (e >= EE) return;
    int s = ei[e], d = ei[EE + e];
    float r0 = g_nuv[d*2+0] - g_nuv[s*2+0];
    float r1 = g_nuv[d*2+1] - g_nuv[s*2+1];
    float dist = sqrtf(r0*r0 + r1*r1);
    ea[(size_t)e*3+0] = r0;
    ea[(size_t)e*3+1] = r1;
    ea[(size_t)e*3+2] = dist;
    atomicAdd(&g_deg[d], 1);
}

// single-block exclusive scan of degrees -> offsets (+cursor copy), warp-shuffle based
__global__ void k_scan()
{
    __shared__ int warpsum[32];
    __shared__ int warpoff[32];
    int t = threadIdx.x;
    int lane = t & 31, wid = t >> 5;
    int carry = 0;
    for (int base = 0; base < NN; base += 1024){
        int v = (base + t < NN) ? g_deg[base + t] : 0;
        int s = v;
#pragma unroll
        for (int o = 1; o < 32; o <<= 1){
            int n = __shfl_up_sync(0xffffffffu, s, o);
            if (lane >= o) s += n;
        }
        if (lane == 31) warpsum[wid] = s;
        __syncthreads();
        if (wid == 0){
            int ws = warpsum[lane];
            int t2 = ws;
#pragma unroll
            for (int o = 1; o < 32; o <<= 1){
                int n = __shfl_up_sync(0xffffffffu, t2, o);
                if (lane >= o) t2 += n;
            }
            warpoff[lane] = t2 - ws;
            if (lane == 31) warpsum[0] = t2;
        }
        __syncthreads();
        int tile_total = warpsum[0];
        if (base + t < NN){
            int ex = carry + warpoff[wid] + s - v;
            g_off[base + t] = ex;
            g_cursor[base + t] = ex;
        }
        __syncthreads();
        carry += tile_total;
    }
    if (t == 0) g_off[NN] = carry;
}

__global__ void k_scatter(const int* __restrict__ ei)
{
    int e = blockIdx.x*blockDim.x + threadIdx.x;
    if (e >= EE) return;
    int d = ei[EE + e];
    int pos = atomicAdd(&g_cursor[d], 1);
    g_csr[pos] = e;
}

// per-edge attention logits; one warp per edge
__global__ void k_logits(const int* __restrict__ ei,
                         const float* __restrict__ lew, const float* __restrict__ att)
{
    __shared__ float s_lew[768];
    __shared__ float s_att[256];
    int t = threadIdx.x;
    s_att[t] = att[t];
    s_lew[t]       = lew[t];
    s_lew[t + 256] = lew[t + 256];
    s_lew[t + 512] = lew[t + 512];
    __syncthreads();

    int e = blockIdx.x*8 + (t >> 5);
    if (e >= EE) return;
    int lane = t & 31;
    int s = ei[e], d = ei[EE + e];

    float r0 = g_nuv[d*2+0] - g_nuv[s*2+0];
    float r1 = g_nuv[d*2+1] - g_nuv[s*2+1];
    float dist = sqrtf(r0*r0 + r1*r1);

    const float4* xl4 = (const float4*)(g_xl + (size_t)s*CC);
    const float4* xr4 = (const float4*)(g_xr + (size_t)d*CC);
    float4 a0 = xl4[lane*2], a1 = xl4[lane*2+1];
    float4 b0 = xr4[lane*2], b1 = xr4[lane*2+1];
    float xs[8] = { a0.x+b0.x, a0.y+b0.y, a0.z+b0.z, a0.w+b0.w,
                    a1.x+b1.x, a1.y+b1.y, a1.z+b1.z, a1.w+b1.w };

    float part = 0.f;
    int c0 = lane*8;
#pragma unroll
    for (int j=0;j<8;j++){
        int c = c0 + j;
        float ee2 = r0*s_lew[c*3+0] + r1*s_lew[c*3+1] + dist*s_lew[c*3+2];
        float z = xs[j] + ee2;
        z = (z > 0.f) ? z : 0.2f*z;
        part += z * s_att[c];
    }
    part += __shfl_xor_sync(0xffffffffu, part, 4);
    part += __shfl_xor_sync(0xffffffffu, part, 2);
    part += __shfl_xor_sync(0xffffffffu, part, 1);
    if ((lane & 7) == 0){
        int h = lane >> 3;
        g_logits[(size_t)e*HH + h] = part;
        atomicMax(&g_maxenc[d*HH + h], encf(part));
    }
}

__global__ void k_exp(const int* __restrict__ ei)
{
    int e = blockIdx.x*blockDim.x + threadIdx.x;
    if (e >= EE) return;
    int d = ei[EE + e];
    float4 lg = *(float4*)(g_logits + (size_t)e*HH);
    float4 ex;
    ex.x = expf(lg.x - decf(g_maxenc[d*HH+0]));
    ex.y = expf(lg.y - decf(g_maxenc[d*HH+1]));
    ex.z = expf(lg.z - decf(g_maxenc[d*HH+2]));
    ex.w = expf(lg.w - decf(g_maxenc[d*HH+3]));
    *(float4*)(g_logits + (size_t)e*HH) = ex;
    atomicAdd(&g_sum[d*HH+0], ex.x);
    atomicAdd(&g_sum[d*HH+1], ex.y);
    atomicAdd(&g_sum[d*HH+2], ex.z);
    atomicAdd(&g_sum[d*HH+3], ex.w);
}

__global__ void k_alpha(const int* __restrict__ ei, float* __restrict__ alpha_out)
{
    int e = blockIdx.x*blockDim.x + threadIdx.x;
    if (e >= EE) return;
    int d = ei[EE + e];
    float4 ex = *(float4*)(g_logits + (size_t)e*HH);
    float4 al;
    al.x = ex.x / (g_sum[d*HH+0] + 1e-16f);
    al.y = ex.y / (g_sum[d*HH+1] + 1e-16f);
    al.z = ex.z / (g_sum[d*HH+2] + 1e-16f);
    al.w = ex.w / (g_sum[d*HH+3] + 1e-16f);
    *(float4*)(alpha_out + (size_t)e*HH) = al;
}

// CSR gather-aggregation + LN + residual + SiLU  (one block per dst node)
__global__ void k_agg(const int* __restrict__ ei, const float* __restrict__ alpha,
                      const float* __restrict__ convb, const float* __restrict__ ng,
                      const float* __restrict__ nb)
{
    int n = blockIdx.x;
    int c = threadIdx.x;        // 256
    int h = c >> 6;
    int st = g_off[n], en = g_off[n+1];
    float acc = 0.f;
    for (int i=st; i<en; i++){
        int e = g_csr[i];
        int s = ei[e];
        acc += alpha[(size_t)e*HH + h] * g_xl[(size_t)s*CC + c];
    }
    float v = acc + convb[c];
    float mean = blockSum256(v) * (1.f/256.f);
    float dv = v - mean;
    float var = blockSum256(dv*dv) * (1.f/256.f);
    float o = dv * rsqrtf(var + 1e-5f) * ng[c] + nb[c];
    float tt = o + g_ident[(size_t)n*CC + c];
    g_pre[(size_t)n*CC + c] = tt / (1.f + expf(-tt));
}

// ---------------- launch ----------------
extern "C" void kernel_launch(void* const* d_in, const int* in_sizes, int n_in,
                              void* d_out, int out_size)
{
    const float* x        = (const float*)d_in[0];
    const float* kpts     = (const float*)d_in[1];
    const float* pts3d    = (const float*)d_in[2];
    const float* pe_w1    = (const float*)d_in[3];
    const float* pe_b1    = (const float*)d_in[4];
    const float* pe_g1    = (const float*)d_in[5];
    const float* pe_bn1   = (const float*)d_in[6];
    const float* pe_w2    = (const float*)d_in[7];
    const float* pe_b2    = (const float*)d_in[8];
    const float* pe_g2    = (const float*)d_in[9];
    const float* pe_bn2   = (const float*)d_in[10];
    const float* lin_l_w  = (const float*)d_in[11];
    const float* lin_l_b  = (const float*)d_in[12];
    const float* lin_r_w  = (const float*)d_in[13];
    const float* lin_r_b  = (const float*)d_in[14];
    const float* lin_edge = (const float*)d_in[15];
    const float* att      = (const float*)d_in[16];
    const float* conv_b   = (const float*)d_in[17];
    const float* norm_g   = (const float*)d_in[18];
    const float* norm_b   = (const float*)d_in[19];
    const float* res_w    = (const float*)d_in[20];
    const float* res_b    = (const float*)d_in[21];
    const float* proj_w   = (const float*)d_in[22];
    const float* proj_b   = (const float*)d_in[23];
    const int*   ei       = (const int*)d_in[24];

    float* out       = (float*)d_out;
    float* alpha_out = out + (size_t)NN*CC;          // [E,4]
    float* ea_out    = alpha_out + (size_t)EE*HH;    // [E,3]

    float *p_xcomb, *p_xl, *p_xr, *p_ident, *p_pre;
    cudaGetSymbolAddress((void**)&p_xcomb, g_xcomb);
    cudaGetSymbolAddress((void**)&p_xl,    g_xl);
    cudaGetSymbolAddress((void**)&p_xr,    g_xr);
    cudaGetSymbolAddress((void**)&p_ident, g_ident);
    cudaGetSymbolAddress((void**)&p_pre,   g_pre);

    const int GEMM_SMEM = 128*136*4;   // 69632 B
    cudaFuncSetAttribute(k_tcgemm2, cudaFuncAttributeMaxDynamicSharedMemorySize, GEMM_SMEM);

    k_init<<<256, 256>>>();
    k_pos<<<(NN + 7)/8, 256>>>(x, kpts, pts3d,
                               pe_w1, pe_b1, pe_g1, pe_bn1,
                               pe_w2, pe_b2, pe_g2, pe_bn2);

    // fused lin_l + lin_r + res GEMMs (tf32 tensor cores, 128x128 tiles)
    dim3 g3((NN + 127)/128, 6);
    k_tcgemm2<<<g3, 256, GEMM_SMEM>>>(p_xcomb, lin_l_w, lin_r_w, res_w,
                                      lin_l_b, lin_r_b, res_b,
                                      p_xl, p_xr, p_ident, NN);

    k_edgeattr<<<(EE + 255)/256, 256>>>(ei, ea_out);
    k_scan<<<1, 1024>>>();
    k_scatter<<<(EE + 255)/256, 256>>>(ei);

    k_logits<<<(EE + 7)/8, 256>>>(ei, lin_edge, att);
    k_exp<<<(EE + 255)/256, 256>>>(ei);
    k_alpha<<<(EE + 255)/256, 256>>>(ei, alpha_out);

    k_agg<<<NN, 256>>>(ei, alpha_out, conv_b, norm_g, norm_b);

    // projector GEMM
    dim3 g1((NN + 127)/128, 2);
    k_tcgemm2<<<g1, 256, GEMM_SMEM>>>(p_pre, proj_w, proj_w, proj_w,
                                      proj_b, proj_b, proj_b,
                                      out, out, out, NN);
}

// round 6
// speedup vs baseline: 1.3214x; 1.0901x over previous
#include <cuda_runtime.h>
#include <cuda_bf16.h>
#include <mma.h>
#include <math.h>

using namespace nvcuda;

// Problem constants
#define NN 50000
#define EE 800000
#define HH 4
#define FF 64
#define CC 256   // H*F == CIN
#define CAPW 64  // per-warp cached degree; fallback to global beyond

// ---------------- device scratch (static, no allocation) ----------------
__device__ float    g_xcomb [(size_t)NN*CC];
__device__ float    g_xl    [(size_t)NN*CC];
__device__ float    g_xr    [(size_t)NN*CC];
__device__ float    g_ident [(size_t)NN*CC];
__device__ float    g_pre   [(size_t)NN*CC];
__device__ float    g_logits[(size_t)EE*HH];   // high-degree fallback (CSR-slot indexed)
__device__ float    g_nuv   [(size_t)NN*2];
__device__ int      g_deg   [NN+1];
__device__ int      g_off   [NN+1];
__device__ int      g_cursor[NN+1];
__device__ int      g_csr   [EE];

// ---------------- helpers ----------------
__device__ __forceinline__ float wsum(float v){
#pragma unroll
    for (int o=16;o>0;o>>=1) v += __shfl_xor_sync(0xffffffffu, v, o);
    return v;
}

// ---------------- kernels ----------------
__global__ void k_init(){
    int i = blockIdx.x*blockDim.x + threadIdx.x;
    int stride = gridDim.x*blockDim.x;
    for (int j=i; j<NN+1; j+=stride) g_deg[j]=0;
}

// positional encoder + build x_comb. One warp per node.
__global__ void k_pos(const float* __restrict__ x, const float* __restrict__ kpts,
                      const float* __restrict__ pts,
                      const float* __restrict__ w1, const float* __restrict__ b1,
                      const float* __restrict__ g1, const float* __restrict__ bn1,
                      const float* __restrict__ w2, const float* __restrict__ b2,
                      const float* __restrict__ g2, const float* __restrict__ bn2)
{
    int node = (blockIdx.x*blockDim.x + threadIdx.x) >> 5;
    int lane = threadIdx.x & 31;
    if (node >= NN) return;
    float u  = kpts[node*2+0] * (1.f/1216.f);
    float v  = kpts[node*2+1] * (1.f/352.f);
    float dep = fminf(fmaxf(pts[node*3+2], 0.1f), 100.f);
    if (lane == 0){ g_nuv[node*2]=u; g_nuv[node*2+1]=v; }

    float a = w1[lane*3+0]*u + w1[lane*3+1]*v + w1[lane*3+2]*dep + b1[lane];
    float m = wsum(a) * (1.f/32.f);
    float d0 = a - m;
    float var = wsum(d0*d0) * (1.f/32.f);
    float hn = d0 * rsqrtf(var + 1e-5f) * g1[lane] + bn1[lane];
    float h = hn / (1.f + expf(-hn));

    float acc0 = b2[lane], acc1 = b2[lane+32];
#pragma unroll
    for (int k=0;k<32;k++){
        float hk = __shfl_sync(0xffffffffu, h, k);
        acc0 += hk * w2[lane*32 + k];
        acc1 += hk * w2[(lane+32)*32 + k];
    }
    float m2 = wsum(acc0 + acc1) * (1.f/64.f);
    float e0 = acc0 - m2, e1 = acc1 - m2;
    float var2 = wsum(e0*e0 + e1*e1) * (1.f/64.f);
    float rs = rsqrtf(var2 + 1e-5f);
    float p0 = e0*rs*g2[lane]    + bn2[lane];
    float p1 = e1*rs*g2[lane+32] + bn2[lane+32];

    size_t base = (size_t)node * CC;
    g_xcomb[base + 192 + lane] = p0;
    g_xcomb[base + 224 + lane] = p1;
#pragma unroll
    for (int j=lane; j<192; j+=32) g_xcomb[base + j] = x[(size_t)node*192 + j];
}

// ---------------- tf32 tensor-core GEMM, 128x128 block tile ----------------
// Operands pre-rounded to tf32 at smem-store time (no in-loop conversion).
__global__ void k_tcgemm2(const float* __restrict__ A,
                          const float* __restrict__ W0, const float* __restrict__ W1,
                          const float* __restrict__ W2,
                          const float* __restrict__ b0, const float* __restrict__ b1,
                          const float* __restrict__ b2,
                          float* __restrict__ C0, float* __restrict__ C1,
                          float* __restrict__ C2, int M)
{
    extern __shared__ float sm[];
    float* As = sm;             // [128][36]
    float* Ws = sm + 128*36;    // [128][36]

    int t  = threadIdx.x;
    int m0 = blockIdx.x * 128;
    int tgt = blockIdx.y >> 1;
    int c0  = (blockIdx.y & 1) * 128;

    const float* W    = (tgt == 0) ? W0 : (tgt == 1) ? W1 : W2;
    const float* bias = (tgt == 0) ? b0 : (tgt == 1) ? b1 : b2;
    float*       C    = (tgt == 0) ? C0 : (tgt == 1) ? C1 : C2;

    int warp = t >> 5;
    int r  = (warp & 3) * 32;
    int cb = (warp >> 2) * 64;

    wmma::fragment<wmma::accumulator, 16, 16, 8, float> acc[2][4];
#pragma unroll
    for (int i=0;i<2;i++)
#pragma unroll
        for (int j=0;j<4;j++) wmma::fill_fragment(acc[i][j], 0.f);

    for (int k0 = 0; k0 < CC; k0 += 32){
#pragma unroll
        for (int j = 0; j < 4; j++){
            int id  = t + j * 256;
            int row = id >> 3;
            int col = (id & 7) * 4;
            float4 av = make_float4(0.f,0.f,0.f,0.f);
            if (m0 + row < M)
                av = *(const float4*)&A[(size_t)(m0 + row) * CC + k0 + col];
            av.x = wmma::__float_to_tf32(av.x); av.y = wmma::__float_to_tf32(av.y);
            av.z = wmma::__float_to_tf32(av.z); av.w = wmma::__float_to_tf32(av.w);
            *(float4*)&As[row*36 + col] = av;
            float4 wv = *(const float4*)&W[(size_t)(c0 + row) * CC + k0 + col];
            wv.x = wmma::__float_to_tf32(wv.x); wv.y = wmma::__float_to_tf32(wv.y);
            wv.z = wmma::__float_to_tf32(wv.z); wv.w = wmma::__float_to_tf32(wv.w);
            *(float4*)&Ws[row*36 + col] = wv;
        }
        __syncthreads();

#pragma unroll
        for (int kk = 0; kk < 32; kk += 8){
            wmma::fragment<wmma::matrix_a, 16, 16, 8, wmma::precision::tf32, wmma::row_major> af[2];
            wmma::fragment<wmma::matrix_b, 16, 16, 8, wmma::precision::tf32, wmma::col_major> bf[4];
#pragma unroll
            for (int i = 0; i < 2; i++)
                wmma::load_matrix_sync(af[i], &As[(r + 16*i)*36 + kk], 36);
#pragma unroll
            for (int j = 0; j < 4; j++)
                wmma::load_matrix_sync(bf[j], &Ws[(cb + 16*j)*36 + kk], 36);
#pragma unroll
            for (int i = 0; i < 2; i++)
#pragma unroll
                for (int j = 0; j < 4; j++)
                    wmma::mma_sync(acc[i][j], af[i], bf[j], acc[i][j]);
        }
        __syncthreads();
    }

    float* Cs = sm;  // [128][136] aliases As/Ws
#pragma unroll
    for (int i = 0; i < 2; i++)
#pragma unroll
        for (int j = 0; j < 4; j++)
            wmma::store_matrix_sync(&Cs[(r + 16*i)*136 + cb + 16*j], acc[i][j], 136, wmma::mem_row_major);
    __syncthreads();

    int col4 = (t & 31) * 4;
    int rb   = t >> 5;
    float4 bv = *(const float4*)&bias[c0 + col4];
#pragma unroll
    for (int i = 0; i < 16; i++){
        int row = rb + i * 8;
        int m = m0 + row;
        if (m < M){
            float4 v = *(float4*)&Cs[row*136 + col4];
            v.x += bv.x; v.y += bv.y; v.z += bv.z; v.w += bv.w;
            *(float4*)&C[(size_t)m * CC + c0 + col4] = v;
        }
    }
}

// edge_attr output + degree histogram
__global__ void k_edgeattr(const int* __restrict__ ei, float* __restrict__ ea)
{
    int e = blockIdx.x*blockDim.x + threadIdx.x;
    if (e >= EE) return;
    int s = ei[e], d = ei[EE + e];
    float r0 = g_nuv[d*2+0] - g_nuv[s*2+0];
    float r1 = g_nuv[d*2+1] - g_nuv[s*2+1];
    float dist = sqrtf(r0*r0 + r1*r1);
    ea[(size_t)e*3+0] = r0;
    ea[(size_t)e*3+1] = r1;
    ea[(size_t)e*3+2] = dist;
    atomicAdd(&g_deg[d], 1);
}

// single-block exclusive scan of degrees -> offsets (+cursor copy)
__global__ void k_scan()
{
    __shared__ int warpsum[32];
    __shared__ int warpoff[32];
    int t = threadIdx.x;
    int lane = t & 31, wid = t >> 5;
    int carry = 0;
    for (int base = 0; base < NN; base += 1024){
        int v = (base + t < NN) ? g_deg[base + t] : 0;
        int s = v;
#pragma unroll
        for (int o = 1; o < 32; o <<= 1){
            int n = __shfl_up_sync(0xffffffffu, s, o);
            if (lane >= o) s += n;
        }
        if (lane == 31) warpsum[wid] = s;
        __syncthreads();
        if (wid == 0){
            int ws = warpsum[lane];
            int t2 = ws;
#pragma unroll
            for (int o = 1; o < 32; o <<= 1){
                int n = __shfl_up_sync(0xffffffffu, t2, o);
                if (lane >= o) t2 += n;
            }
            warpoff[lane] = t2 - ws;
            if (lane == 31) warpsum[0] = t2;
        }
        __syncthreads();
        int tile_total = warpsum[0];
        if (base + t < NN){
            int ex = carry + warpoff[wid] + s - v;
            g_off[base + t] = ex;
            g_cursor[base + t] = ex;
        }
        __syncthreads();
        carry += tile_total;
    }
    if (t == 0) g_off[NN] = carry;
}

__global__ void k_scatter(const int* __restrict__ ei)
{
    int e = blockIdx.x*blockDim.x + threadIdx.x;
    if (e >= EE) return;
    int d = ei[EE + e];
    int pos = atomicAdd(&g_cursor[d], 1);
    g_csr[pos] = e;
}

// ---------------- warp-per-node fused attention ----------------
// One warp per dst node; lane owns 8 channels (c = lane*8 + j).
// Pass 1: logits per edge (8-lane group reduce per head), running max in regs.
// Pass 2: warp softmax (exp + sum + alpha), alpha cached + written out.
// Pass 3: weighted aggregation + LN + residual + SiLU -> g_pre.
// No block barriers; logits/alpha + csr slice cached in per-warp smem.
__global__ void __launch_bounds__(256)
k_wnode(const int* __restrict__ ei, const float* __restrict__ ea,
        const float* __restrict__ lew, const float* __restrict__ att,
        const float* __restrict__ convb, const float* __restrict__ ng,
        const float* __restrict__ nb, float* __restrict__ alpha_out)
{
    __shared__ float4 s_cache[8][CAPW];   // logits/exp/alpha per edge (4 heads)
    __shared__ int    s_csr  [8][CAPW];

    int w = threadIdx.x >> 5, lane = threadIdx.x & 31;
    int n = blockIdx.x*8 + w;
    if (n >= NN) return;

    int st = g_off[n];
    int deg = g_off[n+1] - st;
    int cbase = lane*8;

    // per-lane parameters (registers)
    float wa[8], l0[8], l1[8], l2[8];
#pragma unroll
    for (int j=0;j<8;j++){
        int c = cbase+j;
        wa[j] = att[c];
        l0[j] = lew[c*3+0]; l1[j] = lew[c*3+1]; l2[j] = lew[c*3+2];
    }
    // xr row for this node
    float xr[8];
    {
        const float4* xr4 = (const float4*)(g_xr + (size_t)n*CC);
        float4 t0 = xr4[lane*2], t1 = xr4[lane*2+1];
        xr[0]=t0.x; xr[1]=t0.y; xr[2]=t0.z; xr[3]=t0.w;
        xr[4]=t1.x; xr[5]=t1.y; xr[6]=t1.z; xr[7]=t1.w;
    }

    // preload csr slice
    for (int i=lane; i<deg && i<CAPW; i+=32) s_csr[w][i] = g_csr[st+i];
    __syncwarp();

    float m0=-INFINITY, m1=-INFINITY, m2=-INFINITY, m3=-INFINITY;

    // ---- pass 1: logits + running max ----
    for (int i=0; i<deg; i++){
        int e = (i<CAPW) ? s_csr[w][i] : g_csr[st+i];
        int s = ei[e];
        float r0 = ea[(size_t)e*3+0];
        float r1 = ea[(size_t)e*3+1];
        float dd = ea[(size_t)e*3+2];
        const float4* xl4 = (const float4*)(g_xl + (size_t)s*CC);
        float4 a0 = xl4[lane*2], a1 = xl4[lane*2+1];
        float xs[8] = { a0.x+xr[0], a0.y+xr[1], a0.z+xr[2], a0.w+xr[3],
                        a1.x+xr[4], a1.y+xr[5], a1.z+xr[6], a1.w+xr[7] };
        float p = 0.f;
#pragma unroll
        for (int j=0;j<8;j++){
            float z = xs[j] + r0*l0[j] + r1*l1[j] + dd*l2[j];
            z = (z > 0.f) ? z : 0.2f*z;
            p += z * wa[j];
        }
        // reduce over the 8 lanes of each head group
        p += __shfl_xor_sync(0xffffffffu, p, 4);
        p += __shfl_xor_sync(0xffffffffu, p, 2);
        p += __shfl_xor_sync(0xffffffffu, p, 1);
        float h0 = __shfl_sync(0xffffffffu, p, 0);
        float h1 = __shfl_sync(0xffffffffu, p, 8);
        float h2 = __shfl_sync(0xffffffffu, p, 16);
        float h3 = __shfl_sync(0xffffffffu, p, 24);
        if (i < CAPW){
            if (lane < 4){
                float hv = (lane==0)?h0:(lane==1)?h1:(lane==2)?h2:h3;
                ((float*)&s_cache[w][i])[lane] = hv;
            }
        } else {
            if (lane < 4){
                float hv = (lane==0)?h0:(lane==1)?h1:(lane==2)?h2:h3;
                g_logits[(size_t)(st+i)*HH + lane] = hv;
            }
        }
        m0 = fmaxf(m0, h0); m1 = fmaxf(m1, h1);
        m2 = fmaxf(m2, h2); m3 = fmaxf(m3, h3);
    }
    __syncwarp();

    // ---- pass 2: exp + sums ----
    float s0=0.f, s1=0.f, s2=0.f, s3=0.f;
    for (int i=lane; i<deg; i+=32){
        float4 lg = (i<CAPW) ? s_cache[w][i] : *(float4*)&g_logits[(size_t)(st+i)*HH];
        float4 ex;
        ex.x = expf(lg.x - m0); ex.y = expf(lg.y - m1);
        ex.z = expf(lg.z - m2); ex.w = expf(lg.w - m3);
        if (i<CAPW) s_cache[w][i] = ex;
        else *(float4*)&g_logits[(size_t)(st+i)*HH] = ex;
        s0 += ex.x; s1 += ex.y; s2 += ex.z; s3 += ex.w;
    }
    s0 = wsum(s0); s1 = wsum(s1); s2 = wsum(s2); s3 = wsum(s3);
    float i0 = 1.f/(s0+1e-16f), i1 = 1.f/(s1+1e-16f);
    float i2 = 1.f/(s2+1e-16f), i3 = 1.f/(s3+1e-16f);
    __syncwarp();

    // alpha: cache + output
    for (int i=lane; i<deg; i+=32){
        float4 ex = (i<CAPW) ? s_cache[w][i] : *(float4*)&g_logits[(size_t)(st+i)*HH];
        float4 al = make_float4(ex.x*i0, ex.y*i1, ex.z*i2, ex.w*i3);
        if (i<CAPW) s_cache[w][i] = al;
        else *(float4*)&g_logits[(size_t)(st+i)*HH] = al;
        int e = (i<CAPW) ? s_csr[w][i] : g_csr[st+i];
        *(float4*)&alpha_out[(size_t)e*HH] = al;
    }
    __syncwarp();

    // ---- pass 3: aggregation ----
    int hsel = lane >> 3;
    float acc[8] = {0.f,0.f,0.f,0.f,0.f,0.f,0.f,0.f};
    for (int i=0; i<deg; i++){
        int e = (i<CAPW) ? s_csr[w][i] : g_csr[st+i];
        int s = ei[e];
        float al = (i<CAPW) ? ((float*)&s_cache[w][i])[hsel]
                            : g_logits[(size_t)(st+i)*HH + hsel];
        const float4* xl4 = (const float4*)(g_xl + (size_t)s*CC);
        float4 a0 = xl4[lane*2], a1 = xl4[lane*2+1];
        acc[0] += al*a0.x; acc[1] += al*a0.y; acc[2] += al*a0.z; acc[3] += al*a0.w;
        acc[4] += al*a1.x; acc[5] += al*a1.y; acc[6] += al*a1.z; acc[7] += al*a1.w;
    }

    // ---- epilogue: LN + residual + SiLU ----
    float v[8], part = 0.f;
#pragma unroll
    for (int j=0;j<8;j++){ v[j] = acc[j] + convb[cbase+j]; part += v[j]; }
    float mean = wsum(part) * (1.f/256.f);
    float vp = 0.f;
#pragma unroll
    for (int j=0;j<8;j++){ v[j] -= mean; vp += v[j]*v[j]; }
    float var = wsum(vp) * (1.f/256.f);
    float rs = rsqrtf(var + 1e-5f);

    const float4* id4 = (const float4*)(g_ident + (size_t)n*CC);
    float4 d0 = id4[lane*2], d1 = id4[lane*2+1];
    float idv[8] = { d0.x,d0.y,d0.z,d0.w, d1.x,d1.y,d1.z,d1.w };
    float o[8];
#pragma unroll
    for (int j=0;j<8;j++){
        int c = cbase+j;
        float ov = v[j]*rs*ng[c] + nb[c];
        float tt = ov + idv[j];
        o[j] = tt / (1.f + expf(-tt));
    }
    float4* pr4 = (float4*)(g_pre + (size_t)n*CC);
    pr4[lane*2]   = make_float4(o[0],o[1],o[2],o[3]);
    pr4[lane*2+1] = make_float4(o[4],o[5],o[6],o[7]);
}

// ---------------- launch ----------------
extern "C" void kernel_launch(void* const* d_in, const int* in_sizes, int n_in,
                              void* d_out, int out_size)
{
    const float* x        = (const float*)d_in[0];
    const float* kpts     = (const float*)d_in[1];
    const float* pts3d    = (const float*)d_in[2];
    const float* pe_w1    = (const float*)d_in[3];
    const float* pe_b1    = (const float*)d_in[4];
    const float* pe_g1    = (const float*)d_in[5];
    const float* pe_bn1   = (const float*)d_in[6];
    const float* pe_w2    = (const float*)d_in[7];
    const float* pe_b2    = (const float*)d_in[8];
    const float* pe_g2    = (const float*)d_in[9];
    const float* pe_bn2   = (const float*)d_in[10];
    const float* lin_l_w  = (const float*)d_in[11];
    const float* lin_l_b  = (const float*)d_in[12];
    const float* lin_r_w  = (const float*)d_in[13];
    const float* lin_r_b  = (const float*)d_in[14];
    const float* lin_edge = (const float*)d_in[15];
    const float* att      = (const float*)d_in[16];
    const float* conv_b   = (const float*)d_in[17];
    const float* norm_g   = (const float*)d_in[18];
    const float* norm_b   = (const float*)d_in[19];
    const float* res_w    = (const float*)d_in[20];
    const float* res_b    = (const float*)d_in[21];
    const float* proj_w   = (const float*)d_in[22];
    const float* proj_b   = (const float*)d_in[23];
    const int*   ei       = (const int*)d_in[24];

    float* out       = (float*)d_out;
    float* alpha_out = out + (size_t)NN*CC;          // [E,4]
    float* ea_out    = alpha_out + (size_t)EE*HH;    // [E,3]

    float *p_xcomb, *p_xl, *p_xr, *p_ident, *p_pre;
    cudaGetSymbolAddress((void**)&p_xcomb, g_xcomb);
    cudaGetSymbolAddress((void**)&p_xl,    g_xl);
    cudaGetSymbolAddress((void**)&p_xr,    g_xr);
    cudaGetSymbolAddress((void**)&p_ident, g_ident);
    cudaGetSymbolAddress((void**)&p_pre,   g_pre);

    const int GEMM_SMEM = 128*136*4;   // 69632 B
    cudaFuncSetAttribute(k_tcgemm2, cudaFuncAttributeMaxDynamicSharedMemorySize, GEMM_SMEM);

    k_init<<<64, 256>>>();
    k_pos<<<(NN + 7)/8, 256>>>(x, kpts, pts3d,
                               pe_w1, pe_b1, pe_g1, pe_bn1,
                               pe_w2, pe_b2, pe_g2, pe_bn2);

    // fused lin_l + lin_r + res GEMMs (tf32, 128x128 tiles)
    dim3 g3((NN + 127)/128, 6);
    k_tcgemm2<<<g3, 256, GEMM_SMEM>>>(p_xcomb, lin_l_w, lin_r_w, res_w,
                                      lin_l_b, lin_r_b, res_b,
                                      p_xl, p_xr, p_ident, NN);

    k_edgeattr<<<(EE + 255)/256, 256>>>(ei, ea_out);
    k_scan<<<1, 1024>>>();
    k_scatter<<<(EE + 255)/256, 256>>>(ei);

    // fused edge phase: logits + softmax + alpha + aggregation + LN + SiLU
    k_wnode<<<(NN + 7)/8, 256>>>(ei, ea_out, lin_edge, att,
                                 conv_b, norm_g, norm_b, alpha_out);

    // projector GEMM
    dim3 g1((NN + 127)/128, 2);
    k_tcgemm2<<<g1, 256, GEMM_SMEM>>>(p_pre, proj_w, proj_w, proj_w,
                                      proj_b, proj_b, proj_b,
                                      out, out, out, NN);
}

// round 8
// speedup vs baseline: 1.9182x; 1.4516x over previous
#include <cuda_runtime.h>
#include <cuda_bf16.h>
#include <mma.h>
#include <math.h>
#include <cstdint>

using namespace nvcuda;

// Problem constants
#define NN 50000
#define EE 800000
#define HH 4
#define FF 64
#define CC 256   // H*F == CIN
#define CAPW 64  // per-warp cached degree; fallback to global beyond

// ---------------- device scratch (static, no allocation) ----------------
__device__ float    g_xcomb [(size_t)NN*CC];
__device__ float    g_xl    [(size_t)NN*CC];
__device__ float    g_xr    [(size_t)NN*CC];
__device__ float    g_ident [(size_t)NN*CC];
__device__ float    g_pre   [(size_t)NN*CC];
__device__ float    g_logits[(size_t)EE*HH];   // high-degree fallback (CSR-slot indexed)
__device__ float    g_nuv   [(size_t)NN*2];
__device__ float    g_w2t   [32*64];           // transposed pe_w2
__device__ int      g_deg   [NN+1];
__device__ int      g_off   [NN+1];
__device__ int      g_cursor[NN+1];
__device__ int      g_csr   [EE];

// ---------------- helpers ----------------
__device__ __forceinline__ float wsum(float v){
#pragma unroll
    for (int o=16;o>0;o>>=1) v += __shfl_xor_sync(0xffffffffu, v, o);
    return v;
}

__device__ __forceinline__ void cp_async16(unsigned int dst, const float* src, bool full){
    if (full)
        asm volatile("cp.async.cg.shared.global [%0], [%1], 16;" :: "r"(dst), "l"(src));
    else
        asm volatile("cp.async.cg.shared.global [%0], [%1], 16, 0;" :: "r"(dst), "l"(src));
}

// ---------------- kernels ----------------
__global__ void k_init(){
    int i = blockIdx.x*blockDim.x + threadIdx.x;
    int stride = gridDim.x*blockDim.x;
    for (int j=i; j<NN+1; j+=stride) g_deg[j]=0;
}

// transpose pe_w2 (64x32 -> 32x64) for coalesced reads in k_pos
__global__ void k_prep(const float* __restrict__ w2){
    for (int idx=threadIdx.x; idx<2048; idx+=blockDim.x){
        int k = idx >> 6, c = idx & 63;
        g_w2t[idx] = w2[c*32 + k];
    }
}

// positional encoder + build x_comb. One warp per node.
__global__ void k_pos(const float* __restrict__ x, const float* __restrict__ kpts,
                      const float* __restrict__ pts,
                      const float* __restrict__ w1, const float* __restrict__ b1,
                      const float* __restrict__ g1, const float* __restrict__ bn1,
                      const float* __restrict__ b2,
                      const float* __restrict__ g2, const float* __restrict__ bn2)
{
    int node = (blockIdx.x*blockDim.x + threadIdx.x) >> 5;
    int lane = threadIdx.x & 31;
    if (node >= NN) return;
    float u  = kpts[node*2+0] * (1.f/1216.f);
    float v  = kpts[node*2+1] * (1.f/352.f);
    float dep = fminf(fmaxf(pts[node*3+2], 0.1f), 100.f);
    if (lane == 0){ g_nuv[node*2]=u; g_nuv[node*2+1]=v; }

    float a = w1[lane*3+0]*u + w1[lane*3+1]*v + w1[lane*3+2]*dep + b1[lane];
    float m = wsum(a) * (1.f/32.f);
    float d0 = a - m;
    float var = wsum(d0*d0) * (1.f/32.f);
    float hn = d0 * rsqrtf(var + 1e-5f) * g1[lane] + bn1[lane];
    float h = hn / (1.f + expf(-hn));

    float acc0 = b2[lane], acc1 = b2[lane+32];
#pragma unroll
    for (int k=0;k<32;k++){
        float hk = __shfl_sync(0xffffffffu, h, k);
        acc0 += hk * g_w2t[k*64 + lane];        // coalesced row
        acc1 += hk * g_w2t[k*64 + 32 + lane];
    }
    float m2 = wsum(acc0 + acc1) * (1.f/64.f);
    float e0 = acc0 - m2, e1 = acc1 - m2;
    float var2 = wsum(e0*e0 + e1*e1) * (1.f/64.f);
    float rs = rsqrtf(var2 + 1e-5f);
    float p0 = e0*rs*g2[lane]    + bn2[lane];
    float p1 = e1*rs*g2[lane+32] + bn2[lane+32];

    size_t base = (size_t)node * CC;
    g_xcomb[base + 192 + lane] = p0;
    g_xcomb[base + 224 + lane] = p1;
#pragma unroll
    for (int j=lane; j<192; j+=32) g_xcomb[base + j] = x[(size_t)node*192 + j];
}

// ---------------- tf32 tensor-core GEMM, 128x128 tile, cp.async 2-stage ----------------
#define SS (128*36)                 // floats per matrix per stage
#define GEMM_SMEM (2*2*SS*4)        // 73728 B (also covers Cs 128*136*4 = 69632)

__global__ void k_tcgemm2(const float* __restrict__ A,
                          const float* __restrict__ W0, const float* __restrict__ W1,
                          const float* __restrict__ W2,
                          const float* __restrict__ b0, const float* __restrict__ b1,
                          const float* __restrict__ b2,
                          float* __restrict__ C0, float* __restrict__ C1,
                          float* __restrict__ C2, int M)
{
    extern __shared__ float sm[];

    int t  = threadIdx.x;
    int m0 = blockIdx.x * 128;
    int tgt = blockIdx.y >> 1;
    int c0  = (blockIdx.y & 1) * 128;

    const float* W    = (tgt == 0) ? W0 : (tgt == 1) ? W1 : W2;
    const float* bias = (tgt == 0) ? b0 : (tgt == 1) ? b1 : b2;
    float*       C    = (tgt == 0) ? C0 : (tgt == 1) ? C1 : C2;

    int warp = t >> 5;
    int r  = (warp & 3) * 32;
    int cb = (warp >> 2) * 64;

    unsigned int smb = (unsigned int)__cvta_generic_to_shared(sm);

    // per-thread load coords (4 chunks of 16B)
    int rows[4], cols[4];
#pragma unroll
    for (int j=0;j<4;j++){
        int id = t + j*256;
        rows[j] = id >> 3;
        cols[j] = (id & 7) * 4;
    }

    wmma::fragment<wmma::accumulator, 16, 16, 8, float> acc[2][4];
#pragma unroll
    for (int i=0;i<2;i++)
#pragma unroll
        for (int j=0;j<4;j++) wmma::fill_fragment(acc[i][j], 0.f);

    // issue one stage of async copies
    auto issue = [&](int k0, int s){
#pragma unroll
        for (int j=0;j<4;j++){
            int row = rows[j], col = cols[j];
            bool vA = (m0 + row < M);
            const float* srcA = &A[(size_t)((vA ? m0 + row : 0)) * CC + k0 + col];
            cp_async16(smb + (unsigned int)((s*2*SS + row*36 + col)*4), srcA, vA);
            const float* srcW = &W[(size_t)(c0 + row) * CC + k0 + col];
            cp_async16(smb + (unsigned int)((s*2*SS + SS + row*36 + col)*4), srcW, true);
        }
        asm volatile("cp.async.commit_group;" ::: "memory");
    };

    issue(0, 0);

    for (int it = 0; it < 8; ++it){
        int s = it & 1;
        if (it < 7) issue((it+1)*32, s^1);
        if (it < 7) asm volatile("cp.async.wait_group 1;" ::: "memory");
        else        asm volatile("cp.async.wait_group 0;" ::: "memory");
        __syncthreads();

        float* As = sm + s*2*SS;
        float* Ws = As + SS;
#pragma unroll
        for (int kk = 0; kk < 32; kk += 8){
            wmma::fragment<wmma::matrix_a, 16, 16, 8, wmma::precision::tf32, wmma::row_major> af[2];
            wmma::fragment<wmma::matrix_b, 16, 16, 8, wmma::precision::tf32, wmma::col_major> bf[4];
#pragma unroll
            for (int i = 0; i < 2; i++){
                wmma::load_matrix_sync(af[i], &As[(r + 16*i)*36 + kk], 36);
#pragma unroll
                for (int q = 0; q < af[i].num_elements; q++)
                    af[i].x[q] = wmma::__float_to_tf32(af[i].x[q]);
            }
#pragma unroll
            for (int j = 0; j < 4; j++){
                wmma::load_matrix_sync(bf[j], &Ws[(cb + 16*j)*36 + kk], 36);
#pragma unroll
                for (int q = 0; q < bf[j].num_elements; q++)
                    bf[j].x[q] = wmma::__float_to_tf32(bf[j].x[q]);
            }
#pragma unroll
            for (int i = 0; i < 2; i++)
#pragma unroll
                for (int j = 0; j < 4; j++)
                    wmma::mma_sync(acc[i][j], af[i], bf[j], acc[i][j]);
        }
        __syncthreads();
    }

    float* Cs = sm;  // [128][136] aliases both stages
#pragma unroll
    for (int i = 0; i < 2; i++)
#pragma unroll
        for (int j = 0; j < 4; j++)
            wmma::store_matrix_sync(&Cs[(r + 16*i)*136 + cb + 16*j], acc[i][j], 136, wmma::mem_row_major);
    __syncthreads();

    int col4 = (t & 31) * 4;
    int rb   = t >> 5;
    float4 bv = *(const float4*)&bias[c0 + col4];
#pragma unroll
    for (int i = 0; i < 16; i++){
        int row = rb + i * 8;
        int m = m0 + row;
        if (m < M){
            float4 v = *(float4*)&Cs[row*136 + col4];
            v.x += bv.x; v.y += bv.y; v.z += bv.z; v.w += bv.w;
            *(float4*)&C[(size_t)m * CC + c0 + col4] = v;
        }
    }
}

// edge_attr output + degree histogram
__global__ void k_edgeattr(const int* __restrict__ ei, float* __restrict__ ea)
{
    int e = blockIdx.x*blockDim.x + threadIdx.x;
    if (e >= EE) return;
    int s = ei[e], d = ei[EE + e];
    float r0 = g_nuv[d*2+0] - g_nuv[s*2+0];
    float r1 = g_nuv[d*2+1] - g_nuv[s*2+1];
    float dist = sqrtf(r0*r0 + r1*r1);
    ea[(size_t)e*3+0] = r0;
    ea[(size_t)e*3+1] = r1;
    ea[(size_t)e*3+2] = dist;
    atomicAdd(&g_deg[d], 1);
}

// single-block exclusive scan of degrees -> offsets (+cursor copy)
__global__ void k_scan()
{
    __shared__ int warpsum[32];
    __shared__ int warpoff[32];
    int t = threadIdx.x;
    int lane = t & 31, wid = t >> 5;
    int carry = 0;
    for (int base = 0; base < NN; base += 1024){
        int v = (base + t < NN) ? g_deg[base + t] : 0;
        int s = v;
#pragma unroll
        for (int o = 1; o < 32; o <<= 1){
            int n = __shfl_up_sync(0xffffffffu, s, o);
            if (lane >= o) s += n;
        }
        if (lane == 31) warpsum[wid] = s;
        __syncthreads();
        if (wid == 0){
            int ws = warpsum[lane];
            int t2 = ws;
#pragma unroll
            for (int o = 1; o < 32; o <<= 1){
                int n = __shfl_up_sync(0xffffffffu, t2, o);
                if (lane >= o) t2 += n;
            }
            warpoff[lane] = t2 - ws;
            if (lane == 31) warpsum[0] = t2;
        }
        __syncthreads();
        int tile_total = warpsum[0];
        if (base + t < NN){
            int ex = carry + warpoff[wid] + s - v;
            g_off[base + t] = ex;
            g_cursor[base + t] = ex;
        }
        __syncthreads();
        carry += tile_total;
    }
    if (t == 0) g_off[NN] = carry;
}

__global__ void k_scatter(const int* __restrict__ ei)
{
    int e = blockIdx.x*blockDim.x + threadIdx.x;
    if (e >= EE) return;
    int d = ei[EE + e];
    int pos = atomicAdd(&g_cursor[d], 1);
    g_csr[pos] = e;
}

// ---------------- warp-per-node fused attention ----------------
__global__ void __launch_bounds__(256)
k_wnode(const int* __restrict__ ei, const float* __restrict__ ea,
        const float* __restrict__ lew, const float* __restrict__ att,
        const float* __restrict__ convb, const float* __restrict__ ng,
        const float* __restrict__ nb, float* __restrict__ alpha_out)
{
    __shared__ float4 s_cache[8][CAPW];
    __shared__ int    s_csr  [8][CAPW];

    int w = threadIdx.x >> 5, lane = threadIdx.x & 31;
    int n = blockIdx.x*8 + w;
    if (n >= NN) return;

    int st = g_off[n];
    int deg = g_off[n+1] - st;
    int cbase = lane*8;

    float wa[8], l0[8], l1[8], l2[8];
#pragma unroll
    for (int j=0;j<8;j++){
        int c = cbase+j;
        wa[j] = att[c];
        l0[j] = lew[c*3+0]; l1[j] = lew[c*3+1]; l2[j] = lew[c*3+2];
    }
    float xr[8];
    {
        const float4* xr4 = (const float4*)(g_xr + (size_t)n*CC);
        float4 t0 = xr4[lane*2], t1 = xr4[lane*2+1];
        xr[0]=t0.x; xr[1]=t0.y; xr[2]=t0.z; xr[3]=t0.w;
        xr[4]=t1.x; xr[5]=t1.y; xr[6]=t1.z; xr[7]=t1.w;
    }

    for (int i=lane; i<deg && i<CAPW; i+=32) s_csr[w][i] = g_csr[st+i];
    __syncwarp();

    float m0=-INFINITY, m1=-INFINITY, m2=-INFINITY, m3=-INFINITY;

    for (int i=0; i<deg; i++){
        int e = (i<CAPW) ? s_csr[w][i] : g_csr[st+i];
        int s = ei[e];
        float r0 = ea[(size_t)e*3+0];
        float r1 = ea[(size_t)e*3+1];
        float dd = ea[(size_t)e*3+2];
        const float4* xl4 = (const float4*)(g_xl + (size_t)s*CC);
        float4 a0 = xl4[lane*2], a1 = xl4[lane*2+1];
        float xs[8] = { a0.x+xr[0], a0.y+xr[1], a0.z+xr[2], a0.w+xr[3],
                        a1.x+xr[4], a1.y+xr[5], a1.z+xr[6], a1.w+xr[7] };
        float p = 0.f;
#pragma unroll
        for (int j=0;j<8;j++){
            float z = xs[j] + r0*l0[j] + r1*l1[j] + dd*l2[j];
            z = (z > 0.f) ? z : 0.2f*z;
            p += z * wa[j];
        }
        p += __shfl_xor_sync(0xffffffffu, p, 4);
        p += __shfl_xor_sync(0xffffffffu, p, 2);
        p += __shfl_xor_sync(0xffffffffu, p, 1);
        float h0 = __shfl_sync(0xffffffffu, p, 0);
        float h1 = __shfl_sync(0xffffffffu, p, 8);
        float h2 = __shfl_sync(0xffffffffu, p, 16);
        float h3 = __shfl_sync(0xffffffffu, p, 24);
        if (i < CAPW){
            if (lane < 4){
                float hv = (lane==0)?h0:(lane==1)?h1:(lane==2)?h2:h3;
                ((float*)&s_cache[w][i])[lane] = hv;
            }
        } else {
            if (lane < 4){
                float hv = (lane==0)?h0:(lane==1)?h1:(lane==2)?h2:h3;
                g_logits[(size_t)(st+i)*HH + lane] = hv;
            }
        }
        m0 = fmaxf(m0, h0); m1 = fmaxf(m1, h1);
        m2 = fmaxf(m2, h2); m3 = fmaxf(m3, h3);
    }
    __syncwarp();

    float s0=0.f, s1=0.f, s2=0.f, s3=0.f;
    for (int i=lane; i<deg; i+=32){
        float4 lg = (i<CAPW) ? s_cache[w][i] : *(float4*)&g_logits[(size_t)(st+i)*HH];
        float4 ex;
        ex.x = expf(lg.x - m0); ex.y = expf(lg.y - m1);
        ex.z = expf(lg.z - m2); ex.w = expf(lg.w - m3);
        if (i<CAPW) s_cache[w][i] = ex;
        else *(float4*)&g_logits[(size_t)(st+i)*HH] = ex;
        s0 += ex.x; s1 += ex.y; s2 += ex.z; s3 += ex.w;
    }
    s0 = wsum(s0); s1 = wsum(s1); s2 = wsum(s2); s3 = wsum(s3);
    float i0 = 1.f/(s0+1e-16f), i1 = 1.f/(s1+1e-16f);
    float i2 = 1.f/(s2+1e-16f), i3 = 1.f/(s3+1e-16f);
    __syncwarp();

    for (int i=lane; i<deg; i+=32){
        float4 ex = (i<CAPW) ? s_cache[w][i] : *(float4*)&g_logits[(size_t)(st+i)*HH];
        float4 al = make_float4(ex.x*i0, ex.y*i1, ex.z*i2, ex.w*i3);
        if (i<CAPW) s_cache[w][i] = al;
        else *(float4*)&g_logits[(size_t)(st+i)*HH] = al;
        int e = (i<CAPW) ? s_csr[w][i] : g_csr[st+i];
        *(float4*)&alpha_out[(size_t)e*HH] = al;
    }
    __syncwarp();

    int hsel = lane >> 3;
    float acc[8] = {0.f,0.f,0.f,0.f,0.f,0.f,0.f,0.f};
    for (int i=0; i<deg; i++){
        int e = (i<CAPW) ? s_csr[w][i] : g_csr[st+i];
        int s = ei[e];
        float al = (i<CAPW) ? ((float*)&s_cache[w][i])[hsel]
                            : g_logits[(size_t)(st+i)*HH + hsel];
        const float4* xl4 = (const float4*)(g_xl + (size_t)s*CC);
        float4 a0 = xl4[lane*2], a1 = xl4[lane*2+1];
        acc[0] += al*a0.x; acc[1] += al*a0.y; acc[2] += al*a0.z; acc[3] += al*a0.w;
        acc[4] += al*a1.x; acc[5] += al*a1.y; acc[6] += al*a1.z; acc[7] += al*a1.w;
    }

    float v[8], part = 0.f;
#pragma unroll
    for (int j=0;j<8;j++){ v[j] = acc[j] + convb[cbase+j]; part += v[j]; }
    float mean = wsum(part) * (1.f/256.f);
    float vp = 0.f;
#pragma unroll
    for (int j=0;j<8;j++){ v[j] -= mean; vp += v[j]*v[j]; }
    float var = wsum(vp) * (1.f/256.f);
    float rs = rsqrtf(var + 1e-5f);

    const float4* id4 = (const float4*)(g_ident + (size_t)n*CC);
    float4 d0 = id4[lane*2], d1 = id4[lane*2+1];
    float idv[8] = { d0.x,d0.y,d0.z,d0.w, d1.x,d1.y,d1.z,d1.w };
    float o[8];
#pragma unroll
    for (int j=0;j<8;j++){
        int c = cbase+j;
        float ov = v[j]*rs*ng[c] + nb[c];
        float tt = ov + idv[j];
        o[j] = tt / (1.f + expf(-tt));
    }
    float4* pr4 = (float4*)(g_pre + (size_t)n*CC);
    pr4[lane*2]   = make_float4(o[0],o[1],o[2],o[3]);
    pr4[lane*2+1] = make_float4(o[4],o[5],o[6],o[7]);
}

// ---------------- launch ----------------
extern "C" void kernel_launch(void* const* d_in, const int* in_sizes, int n_in,
                              void* d_out, int out_size)
{
    const float* x        = (const float*)d_in[0];
    const float* kpts     = (const float*)d_in[1];
    const float* pts3d    = (const float*)d_in[2];
    const float* pe_w1    = (const float*)d_in[3];
    const float* pe_b1    = (const float*)d_in[4];
    const float* pe_g1    = (const float*)d_in[5];
    const float* pe_bn1   = (const float*)d_in[6];
    const float* pe_w2    = (const float*)d_in[7];
    const float* pe_b2    = (const float*)d_in[8];
    const float* pe_g2    = (const float*)d_in[9];
    const float* pe_bn2   = (const float*)d_in[10];
    const float* lin_l_w  = (const float*)d_in[11];
    const float* lin_l_b  = (const float*)d_in[12];
    const float* lin_r_w  = (const float*)d_in[13];
    const float* lin_r_b  = (const float*)d_in[14];
    const float* lin_edge = (const float*)d_in[15];
    const float* att      = (const float*)d_in[16];
    const float* conv_b   = (const float*)d_in[17];
    const float* norm_g   = (const float*)d_in[18];
    const float* norm_b   = (const float*)d_in[19];
    const float* res_w    = (const float*)d_in[20];
    const float* res_b    = (const float*)d_in[21];
    const float* proj_w   = (const float*)d_in[22];
    const float* proj_b   = (const float*)d_in[23];
    const int*   ei       = (const int*)d_in[24];

    float* out       = (float*)d_out;
    float* alpha_out = out + (size_t)NN*CC;          // [E,4]
    float* ea_out    = alpha_out + (size_t)EE*HH;    // [E,3]

    float *p_xcomb, *p_xl, *p_xr, *p_ident, *p_pre;
    cudaGetSymbolAddress((void**)&p_xcomb, g_xcomb);
    cudaGetSymbolAddress((void**)&p_xl,    g_xl);
    cudaGetSymbolAddress((void**)&p_xr,    g_xr);
    cudaGetSymbolAddress((void**)&p_ident, g_ident);
    cudaGetSymbolAddress((void**)&p_pre,   g_pre);

    cudaFuncSetAttribute(k_tcgemm2, cudaFuncAttributeMaxDynamicSharedMemorySize, GEMM_SMEM);

    k_init<<<64, 256>>>();
    k_prep<<<1, 256>>>(pe_w2);
    k_pos<<<(NN + 7)/8, 256>>>(x, kpts, pts3d,
                               pe_w1, pe_b1, pe_g1, pe_bn1,
                               pe_b2, pe_g2, pe_bn2);

    // fused lin_l + lin_r + res GEMMs (tf32, 128x128 tiles, cp.async pipelined)
    dim3 g3((NN + 127)/128, 6);
    k_tcgemm2<<<g3, 256, GEMM_SMEM>>>(p_xcomb, lin_l_w, lin_r_w, res_w,
                                      lin_l_b, lin_r_b, res_b,
                                      p_xl, p_xr, p_ident, NN);

    k_edgeattr<<<(EE + 255)/256, 256>>>(ei, ea_out);
    k_scan<<<1, 1024>>>();
    k_scatter<<<(EE + 255)/256, 256>>>(ei);

    // fused edge phase
    k_wnode<<<(NN + 7)/8, 256>>>(ei, ea_out, lin_edge, att,
                                 conv_b, norm_g, norm_b, alpha_out);

    // projector GEMM
    dim3 g1((NN + 127)/128, 2);
    k_tcgemm2<<<g1, 256, GEMM_SMEM>>>(p_pre, proj_w, proj_w, proj_w,
                                      proj_b, proj_b, proj_b,
                                      out, out, out, NN);
}

// round 9
// speedup vs baseline: 2.0758x; 1.0822x over previous
#include <cuda_runtime.h>
#include <cuda_bf16.h>
#include <mma.h>
#include <math.h>
#include <cstdint>

using namespace nvcuda;

// Problem constants
#define NN 50000
#define EE 800000
#define HH 4
#define FF 64
#define CC 256   // H*F == CIN
#define CAPW 64  // per-warp cached degree; fallback to global beyond

// ---------------- device scratch (static, no allocation) ----------------
__device__ float    g_xcomb [(size_t)NN*CC];
__device__ float    g_xl    [(size_t)NN*CC];
__device__ float    g_xr    [(size_t)NN*CC];
__device__ float    g_ident [(size_t)NN*CC];
__device__ float    g_pre   [(size_t)NN*CC];
__device__ float    g_logits[(size_t)EE*HH];   // high-degree fallback (CSR-slot indexed)
__device__ float    g_nuv   [(size_t)NN*2];
__device__ float    g_w2t   [32*64];           // transposed pe_w2
__device__ float    g_wr    [4*CC*CC];         // tf32-rounded weights: lin_l, lin_r, res, proj
__device__ int      g_deg   [NN+1];
__device__ int      g_off   [NN+1];
__device__ int      g_cursor[NN+1];
__device__ int      g_csr   [EE];

// ---------------- helpers ----------------
__device__ __forceinline__ float wsum(float v){
#pragma unroll
    for (int o=16;o>0;o>>=1) v += __shfl_xor_sync(0xffffffffu, v, o);
    return v;
}

__device__ __forceinline__ float rtf32(float x){
    return wmma::__float_to_tf32(x);
}

__device__ __forceinline__ void cp_async16(unsigned int dst, const float* src, bool full){
    if (full)
        asm volatile("cp.async.cg.shared.global [%0], [%1], 16;" :: "r"(dst), "l"(src));
    else
        asm volatile("cp.async.cg.shared.global [%0], [%1], 16, 0;" :: "r"(dst), "l"(src));
}

// ---------------- kernels ----------------
__global__ void k_init(){
    int i = blockIdx.x*blockDim.x + threadIdx.x;
    int stride = gridDim.x*blockDim.x;
    for (int j=i; j<NN+1; j+=stride) g_deg[j]=0;
}

// transpose pe_w2 (64x32 -> 32x64) for coalesced reads in k_pos
__global__ void k_prep(const float* __restrict__ w2){
    for (int idx=threadIdx.x; idx<2048; idx+=blockDim.x){
        int k = idx >> 6, c = idx & 63;
        g_w2t[idx] = w2[c*32 + k];
    }
}

// round the 4 GEMM weight matrices to tf32 once
__global__ void k_roundw(const float* __restrict__ w0, const float* __restrict__ w1,
                         const float* __restrict__ w2, const float* __restrict__ w3){
    int i = blockIdx.x*blockDim.x + threadIdx.x;
    if (i >= CC*CC) return;
    g_wr[i]           = rtf32(w0[i]);
    g_wr[CC*CC + i]   = rtf32(w1[i]);
    g_wr[2*CC*CC + i] = rtf32(w2[i]);
    g_wr[3*CC*CC + i] = rtf32(w3[i]);
}

// positional encoder + build x_comb (tf32-rounded). One warp per node.
__global__ void k_pos(const float* __restrict__ x, const float* __restrict__ kpts,
                      const float* __restrict__ pts,
                      const float* __restrict__ w1, const float* __restrict__ b1,
                      const float* __restrict__ g1, const float* __restrict__ bn1,
                      const float* __restrict__ b2,
                      const float* __restrict__ g2, const float* __restrict__ bn2)
{
    int node = (blockIdx.x*blockDim.x + threadIdx.x) >> 5;
    int lane = threadIdx.x & 31;
    if (node >= NN) return;
    float u  = kpts[node*2+0] * (1.f/1216.f);
    float v  = kpts[node*2+1] * (1.f/352.f);
    float dep = fminf(fmaxf(pts[node*3+2], 0.1f), 100.f);
    if (lane == 0){ g_nuv[node*2]=u; g_nuv[node*2+1]=v; }

    float a = w1[lane*3+0]*u + w1[lane*3+1]*v + w1[lane*3+2]*dep + b1[lane];
    float m = wsum(a) * (1.f/32.f);
    float d0 = a - m;
    float var = wsum(d0*d0) * (1.f/32.f);
    float hn = d0 * rsqrtf(var + 1e-5f) * g1[lane] + bn1[lane];
    float h = hn / (1.f + expf(-hn));

    float acc0 = b2[lane], acc1 = b2[lane+32];
#pragma unroll
    for (int k=0;k<32;k++){
        float hk = __shfl_sync(0xffffffffu, h, k);
        acc0 += hk * g_w2t[k*64 + lane];        // coalesced row
        acc1 += hk * g_w2t[k*64 + 32 + lane];
    }
    float m2 = wsum(acc0 + acc1) * (1.f/64.f);
    float e0 = acc0 - m2, e1 = acc1 - m2;
    float var2 = wsum(e0*e0 + e1*e1) * (1.f/64.f);
    float rs = rsqrtf(var2 + 1e-5f);
    float p0 = e0*rs*g2[lane]    + bn2[lane];
    float p1 = e1*rs*g2[lane+32] + bn2[lane+32];

    size_t base = (size_t)node * CC;
    g_xcomb[base + 192 + lane] = rtf32(p0);
    g_xcomb[base + 224 + lane] = rtf32(p1);
#pragma unroll
    for (int j=lane; j<192; j+=32) g_xcomb[base + j] = rtf32(x[(size_t)node*192 + j]);
}

// ---------------- tf32 tensor-core GEMM, 128x128 tile, cp.async 2-stage ----------------
// Inputs are already tf32-rounded (no in-loop conversion).
#define SS (128*36)                 // floats per matrix per stage
#define GEMM_SMEM (2*2*SS*4)        // 73728 B (also covers Cs 128*136*4 = 69632)

__global__ void __launch_bounds__(256, 2)
k_tcgemm2(const float* __restrict__ A,
          const float* __restrict__ Wbase, int tgt0,
          const float* __restrict__ b0, const float* __restrict__ b1,
          const float* __restrict__ b2,
          float* __restrict__ C0, float* __restrict__ C1,
          float* __restrict__ C2, int M)
{
    extern __shared__ float sm[];

    int t  = threadIdx.x;
    int m0 = blockIdx.x * 128;
    int tgt = blockIdx.y >> 1;
    int c0  = (blockIdx.y & 1) * 128;

    const float* W    = Wbase + (size_t)(tgt0 + tgt)*CC*CC;
    const float* bias = (tgt == 0) ? b0 : (tgt == 1) ? b1 : b2;
    float*       C    = (tgt == 0) ? C0 : (tgt == 1) ? C1 : C2;

    int warp = t >> 5;
    int r  = (warp & 3) * 32;
    int cb = (warp >> 2) * 64;

    unsigned int smb = (unsigned int)__cvta_generic_to_shared(sm);

    // per-thread load coords (4 chunks of 16B)
    int rows[4], cols[4];
#pragma unroll
    for (int j=0;j<4;j++){
        int id = t + j*256;
        rows[j] = id >> 3;
        cols[j] = (id & 7) * 4;
    }

    wmma::fragment<wmma::accumulator, 16, 16, 8, float> acc[2][4];
#pragma unroll
    for (int i=0;i<2;i++)
#pragma unroll
        for (int j=0;j<4;j++) wmma::fill_fragment(acc[i][j], 0.f);

    auto issue = [&](int k0, int s){
#pragma unroll
        for (int j=0;j<4;j++){
            int row = rows[j], col = cols[j];
            bool vA = (m0 + row < M);
            const float* srcA = &A[(size_t)((vA ? m0 + row : 0)) * CC + k0 + col];
            cp_async16(smb + (unsigned int)((s*2*SS + row*36 + col)*4), srcA, vA);
            const float* srcW = &W[(size_t)(c0 + row) * CC + k0 + col];
            cp_async16(smb + (unsigned int)((s*2*SS + SS + row*36 + col)*4), srcW, true);
        }
        asm volatile("cp.async.commit_group;" ::: "memory");
    };

    issue(0, 0);

    for (int it = 0; it < 8; ++it){
        int s = it & 1;
        if (it < 7) issue((it+1)*32, s^1);
        if (it < 7) asm volatile("cp.async.wait_group 1;" ::: "memory");
        else        asm volatile("cp.async.wait_group 0;" ::: "memory");
        __syncthreads();

        float* As = sm + s*2*SS;
        float* Ws = As + SS;
#pragma unroll
        for (int kk = 0; kk < 32; kk += 8){
            wmma::fragment<wmma::matrix_a, 16, 16, 8, wmma::precision::tf32, wmma::row_major> af[2];
            wmma::fragment<wmma::matrix_b, 16, 16, 8, wmma::precision::tf32, wmma::col_major> bf[4];
#pragma unroll
            for (int i = 0; i < 2; i++)
                wmma::load_matrix_sync(af[i], &As[(r + 16*i)*36 + kk], 36);
#pragma unroll
            for (int j = 0; j < 4; j++)
                wmma::load_matrix_sync(bf[j], &Ws[(cb + 16*j)*36 + kk], 36);
#pragma unroll
            for (int i = 0; i < 2; i++)
#pragma unroll
                for (int j = 0; j < 4; j++)
                    wmma::mma_sync(acc[i][j], af[i], bf[j], acc[i][j]);
        }
        __syncthreads();
    }

    float* Cs = sm;  // [128][136] aliases both stages
#pragma unroll
    for (int i = 0; i < 2; i++)
#pragma unroll
        for (int j = 0; j < 4; j++)
            wmma::store_matrix_sync(&Cs[(r + 16*i)*136 + cb + 16*j], acc[i][j], 136, wmma::mem_row_major);
    __syncthreads();

    int col4 = (t & 31) * 4;
    int rb   = t >> 5;
    float4 bv = *(const float4*)&bias[c0 + col4];
#pragma unroll
    for (int i = 0; i < 16; i++){
        int row = rb + i * 8;
        int m = m0 + row;
        if (m < M){
            float4 v = *(float4*)&Cs[row*136 + col4];
            v.x += bv.x; v.y += bv.y; v.z += bv.z; v.w += bv.w;
            *(float4*)&C[(size_t)m * CC + c0 + col4] = v;
        }
    }
}

// edge_attr output + degree histogram
__global__ void k_edgeattr(const int* __restrict__ ei, float* __restrict__ ea)
{
    int e = blockIdx.x*blockDim.x + threadIdx.x;
    if (e >= EE) return;
    int s = ei[e], d = ei[EE + e];
    float r0 = g_nuv[d*2+0] - g_nuv[s*2+0];
    float r1 = g_nuv[d*2+1] - g_nuv[s*2+1];
    float dist = sqrtf(r0*r0 + r1*r1);
    ea[(size_t)e*3+0] = r0;
    ea[(size_t)e*3+1] = r1;
    ea[(size_t)e*3+2] = dist;
    atomicAdd(&g_deg[d], 1);
}

// single-block exclusive scan of degrees -> offsets (+cursor copy)
__global__ void k_scan()
{
    __shared__ int warpsum[32];
    __shared__ int warpoff[32];
    int t = threadIdx.x;
    int lane = t & 31, wid = t >> 5;
    int carry = 0;
    for (int base = 0; base < NN; base += 1024){
        int v = (base + t < NN) ? g_deg[base + t] : 0;
        int s = v;
#pragma unroll
        for (int o = 1; o < 32; o <<= 1){
            int n = __shfl_up_sync(0xffffffffu, s, o);
            if (lane >= o) s += n;
        }
        if (lane == 31) warpsum[wid] = s;
        __syncthreads();
        if (wid == 0){
            int ws = warpsum[lane];
            int t2 = ws;
#pragma unroll
            for (int o = 1; o < 32; o <<= 1){
                int n = __shfl_up_sync(0xffffffffu, t2, o);
                if (lane >= o) t2 += n;
            }
            warpoff[lane] = t2 - ws;
            if (lane == 31) warpsum[0] = t2;
        }
        __syncthreads();
        int tile_total = warpsum[0];
        if (base + t < NN){
            int ex = carry + warpoff[wid] + s - v;
            g_off[base + t] = ex;
            g_cursor[base + t] = ex;
        }
        __syncthreads();
        carry += tile_total;
    }
    if (t == 0) g_off[NN] = carry;
}

__global__ void k_scatter(const int* __restrict__ ei)
{
    int e = blockIdx.x*blockDim.x + threadIdx.x;
    if (e >= EE) return;
    int d = ei[EE + e];
    int pos = atomicAdd(&g_cursor[d], 1);
    g_csr[pos] = e;
}

// ---------------- warp-per-node fused attention ----------------
__global__ void __launch_bounds__(256)
k_wnode(const int* __restrict__ ei, const float* __restrict__ ea,
        const float* __restrict__ lew, const float* __restrict__ att,
        const float* __restrict__ convb, const float* __restrict__ ng,
        const float* __restrict__ nb, float* __restrict__ alpha_out)
{
    __shared__ float4 s_cache[8][CAPW];
    __shared__ int    s_csr  [8][CAPW];

    int w = threadIdx.x >> 5, lane = threadIdx.x & 31;
    int n = blockIdx.x*8 + w;
    if (n >= NN) return;

    int st = g_off[n];
    int deg = g_off[n+1] - st;
    int cbase = lane*8;

    float wa[8], l0[8], l1[8], l2[8];
#pragma unroll
    for (int j=0;j<8;j++){
        int c = cbase+j;
        wa[j] = att[c];
        l0[j] = lew[c*3+0]; l1[j] = lew[c*3+1]; l2[j] = lew[c*3+2];
    }
    float xr[8];
    {
        const float4* xr4 = (const float4*)(g_xr + (size_t)n*CC);
        float4 t0 = xr4[lane*2], t1 = xr4[lane*2+1];
        xr[0]=t0.x; xr[1]=t0.y; xr[2]=t0.z; xr[3]=t0.w;
        xr[4]=t1.x; xr[5]=t1.y; xr[6]=t1.z; xr[7]=t1.w;
    }

    for (int i=lane; i<deg && i<CAPW; i+=32) s_csr[w][i] = g_csr[st+i];
    __syncwarp();

    float m0=-INFINITY, m1=-INFINITY, m2=-INFINITY, m3=-INFINITY;

    for (int i=0; i<deg; i++){
        int e = (i<CAPW) ? s_csr[w][i] : g_csr[st+i];
        int s = ei[e];
        float r0 = ea[(size_t)e*3+0];
        float r1 = ea[(size_t)e*3+1];
        float dd = ea[(size_t)e*3+2];
        const float4* xl4 = (const float4*)(g_xl + (size_t)s*CC);
        float4 a0 = xl4[lane*2], a1 = xl4[lane*2+1];
        float xs[8] = { a0.x+xr[0], a0.y+xr[1], a0.z+xr[2], a0.w+xr[3],
                        a1.x+xr[4], a1.y+xr[5], a1.z+xr[6], a1.w+xr[7] };
        float p = 0.f;
#pragma unroll
        for (int j=0;j<8;j++){
            float z = xs[j] + r0*l0[j] + r1*l1[j] + dd*l2[j];
            z = (z > 0.f) ? z : 0.2f*z;
            p += z * wa[j];
        }
        p += __shfl_xor_sync(0xffffffffu, p, 4);
        p += __shfl_xor_sync(0xffffffffu, p, 2);
        p += __shfl_xor_sync(0xffffffffu, p, 1);
        float h0 = __shfl_sync(0xffffffffu, p, 0);
        float h1 = __shfl_sync(0xffffffffu, p, 8);
        float h2 = __shfl_sync(0xffffffffu, p, 16);
        float h3 = __shfl_sync(0xffffffffu, p, 24);
        if (i < CAPW){
            if (lane < 4){
                float hv = (lane==0)?h0:(lane==1)?h1:(lane==2)?h2:h3;
                ((float*)&s_cache[w][i])[lane] = hv;
            }
        } else {
            if (lane < 4){
                float hv = (lane==0)?h0:(lane==1)?h1:(lane==2)?h2:h3;
                g_logits[(size_t)(st+i)*HH + lane] = hv;
            }
        }
        m0 = fmaxf(m0, h0); m1 = fmaxf(m1, h1);
        m2 = fmaxf(m2, h2); m3 = fmaxf(m3, h3);
    }
    __syncwarp();

    float s0=0.f, s1=0.f, s2=0.f, s3=0.f;
    for (int i=lane; i<deg; i+=32){
        float4 lg = (i<CAPW) ? s_cache[w][i] : *(float4*)&g_logits[(size_t)(st+i)*HH];
        float4 ex;
        ex.x = expf(lg.x - m0); ex.y = expf(lg.y - m1);
        ex.z = expf(lg.z - m2); ex.w = expf(lg.w - m3);
        if (i<CAPW) s_cache[w][i] = ex;
        else *(float4*)&g_logits[(size_t)(st+i)*HH] = ex;
        s0 += ex.x; s1 += ex.y; s2 += ex.z; s3 += ex.w;
    }
    s0 = wsum(s0); s1 = wsum(s1); s2 = wsum(s2); s3 = wsum(s3);
    float i0 = 1.f/(s0+1e-16f), i1 = 1.f/(s1+1e-16f);
    float i2 = 1.f/(s2+1e-16f), i3 = 1.f/(s3+1e-16f);
    __syncwarp();

    for (int i=lane; i<deg; i+=32){
        float4 ex = (i<CAPW) ? s_cache[w][i] : *(float4*)&g_logits[(size_t)(st+i)*HH];
        float4 al = make_float4(ex.x*i0, ex.y*i1, ex.z*i2, ex.w*i3);
        if (i<CAPW) s_cache[w][i] = al;
        else *(float4*)&g_logits[(size_t)(st+i)*HH] = al;
        int e = (i<CAPW) ? s_csr[w][i] : g_csr[st+i];
        *(float4*)&alpha_out[(size_t)e*HH] = al;
    }
    __syncwarp();

    int hsel = lane >> 3;
    float acc[8] = {0.f,0.f,0.f,0.f,0.f,0.f,0.f,0.f};
    for (int i=0; i<deg; i++){
        int e = (i<CAPW) ? s_csr[w][i] : g_csr[st+i];
        int s = ei[e];
        float al = (i<CAPW) ? ((float*)&s_cache[w][i])[hsel]
                            : g_logits[(size_t)(st+i)*HH + hsel];
        const float4* xl4 = (const float4*)(g_xl + (size_t)s*CC);
        float4 a0 = xl4[lane*2], a1 = xl4[lane*2+1];
        acc[0] += al*a0.x; acc[1] += al*a0.y; acc[2] += al*a0.z; acc[3] += al*a0.w;
        acc[4] += al*a1.x; acc[5] += al*a1.y; acc[6] += al*a1.z; acc[7] += al*a1.w;
    }

    float v[8], part = 0.f;
#pragma unroll
    for (int j=0;j<8;j++){ v[j] = acc[j] + convb[cbase+j]; part += v[j]; }
    float mean = wsum(part) * (1.f/256.f);
    float vp = 0.f;
#pragma unroll
    for (int j=0;j<8;j++){ v[j] -= mean; vp += v[j]*v[j]; }
    float var = wsum(vp) * (1.f/256.f);
    float rs = rsqrtf(var + 1e-5f);

    const float4* id4 = (const float4*)(g_ident + (size_t)n*CC);
    float4 d0 = id4[lane*2], d1 = id4[lane*2+1];
    float idv[8] = { d0.x,d0.y,d0.z,d0.w, d1.x,d1.y,d1.z,d1.w };
    float o[8];
#pragma unroll
    for (int j=0;j<8;j++){
        int c = cbase+j;
        float ov = v[j]*rs*ng[c] + nb[c];
        float tt = ov + idv[j];
        o[j] = rtf32(tt / (1.f + expf(-tt)));   // pre-round for proj GEMM
    }
    float4* pr4 = (float4*)(g_pre + (size_t)n*CC);
    pr4[lane*2]   = make_float4(o[0],o[1],o[2],o[3]);
    pr4[lane*2+1] = make_float4(o[4],o[5],o[6],o[7]);
}

// ---------------- launch ----------------
extern "C" void kernel_launch(void* const* d_in, const int* in_sizes, int n_in,
                              void* d_out, int out_size)
{
    const float* x        = (const float*)d_in[0];
    const float* kpts     = (const float*)d_in[1];
    const float* pts3d    = (const float*)d_in[2];
    const float* pe_w1    = (const float*)d_in[3];
    const float* pe_b1    = (const float*)d_in[4];
    const float* pe_g1    = (const float*)d_in[5];
    const float* pe_bn1   = (const float*)d_in[6];
    const float* pe_w2    = (const float*)d_in[7];
    const float* pe_b2    = (const float*)d_in[8];
    const float* pe_g2    = (const float*)d_in[9];
    const float* pe_bn2   = (const float*)d_in[10];
    const float* lin_l_w  = (const float*)d_in[11];
    const float* lin_l_b  = (const float*)d_in[12];
    const float* lin_r_w  = (const float*)d_in[13];
    const float* lin_r_b  = (const float*)d_in[14];
    const float* lin_edge = (const float*)d_in[15];
    const float* att      = (const float*)d_in[16];
    const float* conv_b   = (const float*)d_in[17];
    const float* norm_g   = (const float*)d_in[18];
    const float* norm_b   = (const float*)d_in[19];
    const float* res_w    = (const float*)d_in[20];
    const float* res_b    = (const float*)d_in[21];
    const float* proj_w   = (const float*)d_in[22];
    const float* proj_b   = (const float*)d_in[23];
    const int*   ei       = (const int*)d_in[24];

    float* out       = (float*)d_out;
    float* alpha_out = out + (size_t)NN*CC;          // [E,4]
    float* ea_out    = alpha_out + (size_t)EE*HH;    // [E,3]

    float *p_xcomb, *p_xl, *p_xr, *p_ident, *p_pre, *p_wr;
    cudaGetSymbolAddress((void**)&p_xcomb, g_xcomb);
    cudaGetSymbolAddress((void**)&p_xl,    g_xl);
    cudaGetSymbolAddress((void**)&p_xr,    g_xr);
    cudaGetSymbolAddress((void**)&p_ident, g_ident);
    cudaGetSymbolAddress((void**)&p_pre,   g_pre);
    cudaGetSymbolAddress((void**)&p_wr,    g_wr);

    cudaFuncSetAttribute(k_tcgemm2, cudaFuncAttributeMaxDynamicSharedMemorySize, GEMM_SMEM);

    k_init<<<64, 256>>>();
    k_prep<<<1, 256>>>(pe_w2);
    k_roundw<<<(CC*CC + 255)/256, 256>>>(lin_l_w, lin_r_w, res_w, proj_w);
    k_pos<<<(NN + 7)/8, 256>>>(x, kpts, pts3d,
                               pe_w1, pe_b1, pe_g1, pe_bn1,
                               pe_b2, pe_g2, pe_bn2);

    // fused lin_l + lin_r + res GEMMs (tf32, 128x128 tiles, cp.async pipelined)
    dim3 g3((NN + 127)/128, 6);
    k_tcgemm2<<<g3, 256, GEMM_SMEM>>>(p_xcomb, p_wr, 0,
                                      lin_l_b, lin_r_b, res_b,
                                      p_xl, p_xr, p_ident, NN);

    k_edgeattr<<<(EE + 255)/256, 256>>>(ei, ea_out);
    k_scan<<<1, 1024>>>();
    k_scatter<<<(EE + 255)/256, 256>>>(ei);

    // fused edge phase
    k_wnode<<<(NN + 7)/8, 256>>>(ei, ea_out, lin_edge, att,
                                 conv_b, norm_g, norm_b, alpha_out);

    // projector GEMM
    dim3 g1((NN + 127)/128, 2);
    k_tcgemm2<<<g1, 256, GEMM_SMEM>>>(p_pre, p_wr, 3,
                                      proj_b, proj_b, proj_b,
                                      out, out, out, NN);
}

// round 10
// speedup vs baseline: 2.0856x; 1.0047x over previous
#include <cuda_runtime.h>
#include <cuda_bf16.h>
#include <mma.h>
#include <math.h>
#include <cstdint>

using namespace nvcuda;

// Problem constants
#define NN 50000
#define EE 800000
#define HH 4
#define FF 64
#define CC 256   // H*F == CIN
#define CAPW 64  // per-warp cached degree; fallback to global beyond

// ---------------- device scratch (static, no allocation) ----------------
__device__ float    g_xcomb [(size_t)NN*CC];
__device__ float    g_xl    [(size_t)NN*CC];
__device__ float    g_xr    [(size_t)NN*CC];
__device__ float    g_ident [(size_t)NN*CC];
__device__ float    g_pre   [(size_t)NN*CC];
__device__ float    g_logits[(size_t)EE*HH];   // high-degree fallback (CSR-slot indexed)
__device__ float    g_nuv   [(size_t)NN*2];
__device__ float    g_w2t   [32*64];           // transposed pe_w2
__device__ float    g_wr    [4*CC*CC];         // tf32-rounded weights: lin_l, lin_r, res, proj
__device__ int      g_deg   [NN+1];
__device__ int      g_off   [NN+1];
__device__ int      g_cursor[NN+1];
__device__ int      g_csr   [EE];

// ---------------- helpers ----------------
__device__ __forceinline__ float wsum(float v){
#pragma unroll
    for (int o=16;o>0;o>>=1) v += __shfl_xor_sync(0xffffffffu, v, o);
    return v;
}

__device__ __forceinline__ float rtf32(float x){
    return wmma::__float_to_tf32(x);
}

__device__ __forceinline__ void cp_async16(unsigned int dst, const float* src, bool full){
    if (full)
        asm volatile("cp.async.cg.shared.global [%0], [%1], 16;" :: "r"(dst), "l"(src));
    else
        asm volatile("cp.async.cg.shared.global [%0], [%1], 16, 0;" :: "r"(dst), "l"(src));
}

// ---------------- kernels ----------------
__global__ void k_init(){
    int i = blockIdx.x*blockDim.x + threadIdx.x;
    int stride = gridDim.x*blockDim.x;
    for (int j=i; j<NN+1; j+=stride) g_deg[j]=0;
}

// transpose pe_w2 (64x32 -> 32x64) for coalesced reads in k_pos
__global__ void k_prep(const float* __restrict__ w2){
    for (int idx=threadIdx.x; idx<2048; idx+=blockDim.x){
        int k = idx >> 6, c = idx & 63;
        g_w2t[idx] = w2[c*32 + k];
    }
}

// round the 4 GEMM weight matrices to tf32 once
__global__ void k_roundw(const float* __restrict__ w0, const float* __restrict__ w1,
                         const float* __restrict__ w2, const float* __restrict__ w3){
    int i = blockIdx.x*blockDim.x + threadIdx.x;
    if (i >= CC*CC) return;
    g_wr[i]           = rtf32(w0[i]);
    g_wr[CC*CC + i]   = rtf32(w1[i]);
    g_wr[2*CC*CC + i] = rtf32(w2[i]);
    g_wr[3*CC*CC + i] = rtf32(w3[i]);
}

// positional encoder + build x_comb (tf32-rounded). One warp per node.
__global__ void k_pos(const float* __restrict__ x, const float* __restrict__ kpts,
                      const float* __restrict__ pts,
                      const float* __restrict__ w1, const float* __restrict__ b1,
                      const float* __restrict__ g1, const float* __restrict__ bn1,
                      const float* __restrict__ b2,
                      const float* __restrict__ g2, const float* __restrict__ bn2)
{
    int node = (blockIdx.x*blockDim.x + threadIdx.x) >> 5;
    int lane = threadIdx.x & 31;
    if (node >= NN) return;
    float u  = kpts[node*2+0] * (1.f/1216.f);
    float v  = kpts[node*2+1] * (1.f/352.f);
    float dep = fminf(fmaxf(pts[node*3+2], 0.1f), 100.f);
    if (lane == 0){ g_nuv[node*2]=u; g_nuv[node*2+1]=v; }

    float a = w1[lane*3+0]*u + w1[lane*3+1]*v + w1[lane*3+2]*dep + b1[lane];
    float m = wsum(a) * (1.f/32.f);
    float d0 = a - m;
    float var = wsum(d0*d0) * (1.f/32.f);
    float hn = d0 * rsqrtf(var + 1e-5f) * g1[lane] + bn1[lane];
    float h = hn / (1.f + expf(-hn));

    float acc0 = b2[lane], acc1 = b2[lane+32];
#pragma unroll
    for (int k=0;k<32;k++){
        float hk = __shfl_sync(0xffffffffu, h, k);
        acc0 += hk * g_w2t[k*64 + lane];
        acc1 += hk * g_w2t[k*64 + 32 + lane];
    }
    float m2 = wsum(acc0 + acc1) * (1.f/64.f);
    float e0 = acc0 - m2, e1 = acc1 - m2;
    float var2 = wsum(e0*e0 + e1*e1) * (1.f/64.f);
    float rs = rsqrtf(var2 + 1e-5f);
    float p0 = e0*rs*g2[lane]    + bn2[lane];
    float p1 = e1*rs*g2[lane+32] + bn2[lane+32];

    size_t base = (size_t)node * CC;
    g_xcomb[base + 192 + lane] = rtf32(p0);
    g_xcomb[base + 224 + lane] = rtf32(p1);
#pragma unroll
    for (int j=lane; j<192; j+=32) g_xcomb[base + j] = rtf32(x[(size_t)node*192 + j]);
}

// ---------------- tf32 tensor-core GEMM, 128x128 tile, cp.async 2-stage ----------------
// Inputs pre-rounded to tf32. Smem stride 40 floats (8-bank rotation, conflict-free).
#define SS (128*40)                 // floats per matrix per stage
#define GEMM_SMEM (2*2*SS*4)        // 81920 B (also covers Cs 128*136*4 = 69632)

__global__ void __launch_bounds__(256, 2)
k_tcgemm2(const float* __restrict__ A,
          const float* __restrict__ Wbase, int tgt0,
          const float* __restrict__ b0, const float* __restrict__ b1,
          const float* __restrict__ b2,
          float* __restrict__ C0, float* __restrict__ C1,
          float* __restrict__ C2, int M)
{
    extern __shared__ float sm[];

    int t  = threadIdx.x;
    int m0 = blockIdx.x * 128;
    int tgt = blockIdx.y >> 1;
    int c0  = (blockIdx.y & 1) * 128;

    const float* W    = Wbase + (size_t)(tgt0 + tgt)*CC*CC;
    const float* bias = (tgt == 0) ? b0 : (tgt == 1) ? b1 : b2;
    float*       C    = (tgt == 0) ? C0 : (tgt == 1) ? C1 : C2;

    int warp = t >> 5;
    int r  = (warp & 3) * 32;
    int cb = (warp >> 2) * 64;

    unsigned int smb = (unsigned int)__cvta_generic_to_shared(sm);

    int rows[4], cols[4];
#pragma unroll
    for (int j=0;j<4;j++){
        int id = t + j*256;
        rows[j] = id >> 3;
        cols[j] = (id & 7) * 4;
    }

    wmma::fragment<wmma::accumulator, 16, 16, 8, float> acc[2][4];
#pragma unroll
    for (int i=0;i<2;i++)
#pragma unroll
        for (int j=0;j<4;j++) wmma::fill_fragment(acc[i][j], 0.f);

    auto issue = [&](int k0, int s){
#pragma unroll
        for (int j=0;j<4;j++){
            int row = rows[j], col = cols[j];
            bool vA = (m0 + row < M);
            const float* srcA = &A[(size_t)((vA ? m0 + row : 0)) * CC + k0 + col];
            cp_async16(smb + (unsigned int)((s*2*SS + row*40 + col)*4), srcA, vA);
            const float* srcW = &W[(size_t)(c0 + row) * CC + k0 + col];
            cp_async16(smb + (unsigned int)((s*2*SS + SS + row*40 + col)*4), srcW, true);
        }
        asm volatile("cp.async.commit_group;" ::: "memory");
    };

    issue(0, 0);

    for (int it = 0; it < 8; ++it){
        int s = it & 1;
        if (it < 7) issue((it+1)*32, s^1);
        if (it < 7) asm volatile("cp.async.wait_group 1;" ::: "memory");
        else        asm volatile("cp.async.wait_group 0;" ::: "memory");
        __syncthreads();

        float* As = sm + s*2*SS;
        float* Ws = As + SS;
#pragma unroll
        for (int kk = 0; kk < 32; kk += 8){
            wmma::fragment<wmma::matrix_a, 16, 16, 8, wmma::precision::tf32, wmma::row_major> af[2];
            wmma::fragment<wmma::matrix_b, 16, 16, 8, wmma::precision::tf32, wmma::col_major> bf[4];
#pragma unroll
            for (int i = 0; i < 2; i++)
                wmma::load_matrix_sync(af[i], &As[(r + 16*i)*40 + kk], 40);
#pragma unroll
            for (int j = 0; j < 4; j++)
                wmma::load_matrix_sync(bf[j], &Ws[(cb + 16*j)*40 + kk], 40);
#pragma unroll
            for (int i = 0; i < 2; i++)
#pragma unroll
                for (int j = 0; j < 4; j++)
                    wmma::mma_sync(acc[i][j], af[i], bf[j], acc[i][j]);
        }
        __syncthreads();
    }

    float* Cs = sm;  // [128][136] aliases both stages
#pragma unroll
    for (int i = 0; i < 2; i++)
#pragma unroll
        for (int j = 0; j < 4; j++)
            wmma::store_matrix_sync(&Cs[(r + 16*i)*136 + cb + 16*j], acc[i][j], 136, wmma::mem_row_major);
    __syncthreads();

    int col4 = (t & 31) * 4;
    int rb   = t >> 5;
    float4 bv = *(const float4*)&bias[c0 + col4];
#pragma unroll
    for (int i = 0; i < 16; i++){
        int row = rb + i * 8;
        int m = m0 + row;
        if (m < M){
            float4 v = *(float4*)&Cs[row*136 + col4];
            v.x += bv.x; v.y += bv.y; v.z += bv.z; v.w += bv.w;
            *(float4*)&C[(size_t)m * CC + c0 + col4] = v;
        }
    }
}

// edge_attr output + degree histogram
__global__ void k_edgeattr(const int* __restrict__ ei, float* __restrict__ ea)
{
    int e = blockIdx.x*blockDim.x + threadIdx.x;
    if (e >= EE) return;
    int s = ei[e], d = ei[EE + e];
    float r0 = g_nuv[d*2+0] - g_nuv[s*2+0];
    float r1 = g_nuv[d*2+1] - g_nuv[s*2+1];
    float dist = sqrtf(r0*r0 + r1*r1);
    ea[(size_t)e*3+0] = r0;
    ea[(size_t)e*3+1] = r1;
    ea[(size_t)e*3+2] = dist;
    atomicAdd(&g_deg[d], 1);
}

// single-block exclusive scan of degrees -> offsets (+cursor copy)
__global__ void k_scan()
{
    __shared__ int warpsum[32];
    __shared__ int warpoff[32];
    int t = threadIdx.x;
    int lane = t & 31, wid = t >> 5;
    int carry = 0;
    for (int base = 0; base < NN; base += 1024){
        int v = (base + t < NN) ? g_deg[base + t] : 0;
        int s = v;
#pragma unroll
        for (int o = 1; o < 32; o <<= 1){
            int n = __shfl_up_sync(0xffffffffu, s, o);
            if (lane >= o) s += n;
        }
        if (lane == 31) warpsum[wid] = s;
        __syncthreads();
        if (wid == 0){
            int ws = warpsum[lane];
            int t2 = ws;
#pragma unroll
            for (int o = 1; o < 32; o <<= 1){
                int n = __shfl_up_sync(0xffffffffu, t2, o);
                if (lane >= o) t2 += n;
            }
            warpoff[lane] = t2 - ws;
            if (lane == 31) warpsum[0] = t2;
        }
        __syncthreads();
        int tile_total = warpsum[0];
        if (base + t < NN){
            int ex = carry + warpoff[wid] + s - v;
            g_off[base + t] = ex;
            g_cursor[base + t] = ex;
        }
        __syncthreads();
        carry += tile_total;
    }
    if (t == 0) g_off[NN] = carry;
}

__global__ void k_scatter(const int* __restrict__ ei)
{
    int e = blockIdx.x*blockDim.x + threadIdx.x;
    if (e >= EE) return;
    int d = ei[EE + e];
    int pos = atomicAdd(&g_cursor[d], 1);
    g_csr[pos] = e;
}

// ---------------- warp-per-node fused attention (2x software-pipelined) ----------------
__global__ void __launch_bounds__(256)
k_wnode(const int* __restrict__ ei, const float* __restrict__ ea,
        const float* __restrict__ lew, const float* __restrict__ att,
        const float* __restrict__ convb, const float* __restrict__ ng,
        const float* __restrict__ nb, float* __restrict__ alpha_out)
{
    __shared__ float4 s_cache[8][CAPW];
    __shared__ int    s_csr  [8][CAPW];

    int w = threadIdx.x >> 5, lane = threadIdx.x & 31;
    int n = blockIdx.x*8 + w;
    if (n >= NN) return;

    int st = g_off[n];
    int deg = g_off[n+1] - st;
    int cbase = lane*8;

    float wa[8], l0[8], l1[8], l2[8];
#pragma unroll
    for (int j=0;j<8;j++){
        int c = cbase+j;
        wa[j] = att[c];
        l0[j] = lew[c*3+0]; l1[j] = lew[c*3+1]; l2[j] = lew[c*3+2];
    }
    float xr[8];
    {
        const float4* xr4 = (const float4*)(g_xr + (size_t)n*CC);
        float4 t0 = xr4[lane*2], t1 = xr4[lane*2+1];
        xr[0]=t0.x; xr[1]=t0.y; xr[2]=t0.z; xr[3]=t0.w;
        xr[4]=t1.x; xr[5]=t1.y; xr[6]=t1.z; xr[7]=t1.w;
    }

    for (int i=lane; i<deg && i<CAPW; i+=32) s_csr[w][i] = g_csr[st+i];
    __syncwarp();

    float m0=-INFINITY, m1=-INFINITY, m2=-INFINITY, m3=-INFINITY;

    // ---- pass 1: logits + running max (2 edges in flight) ----
    int i = 0;
    for (; i+1 < deg; i += 2){
        int eA = (i   < CAPW) ? s_csr[w][i]   : g_csr[st+i];
        int eB = (i+1 < CAPW) ? s_csr[w][i+1] : g_csr[st+i+1];
        int sA = ei[eA], sB = ei[eB];
        float r0A = ea[(size_t)eA*3+0], r1A = ea[(size_t)eA*3+1], ddA = ea[(size_t)eA*3+2];
        float r0B = ea[(size_t)eB*3+0], r1B = ea[(size_t)eB*3+1], ddB = ea[(size_t)eB*3+2];
        const float4* xlA = (const float4*)(g_xl + (size_t)sA*CC);
        const float4* xlB = (const float4*)(g_xl + (size_t)sB*CC);
        float4 a0A = xlA[lane*2], a1A = xlA[lane*2+1];
        float4 a0B = xlB[lane*2], a1B = xlB[lane*2+1];

        float xsA[8] = { a0A.x+xr[0], a0A.y+xr[1], a0A.z+xr[2], a0A.w+xr[3],
                         a1A.x+xr[4], a1A.y+xr[5], a1A.z+xr[6], a1A.w+xr[7] };
        float xsB[8] = { a0B.x+xr[0], a0B.y+xr[1], a0B.z+xr[2], a0B.w+xr[3],
                         a1B.x+xr[4], a1B.y+xr[5], a1B.z+xr[6], a1B.w+xr[7] };
        float pA = 0.f, pB = 0.f;
#pragma unroll
        for (int j=0;j<8;j++){
            float zA = xsA[j] + r0A*l0[j] + r1A*l1[j] + ddA*l2[j];
            zA = (zA > 0.f) ? zA : 0.2f*zA;
            pA += zA * wa[j];
            float zB = xsB[j] + r0B*l0[j] + r1B*l1[j] + ddB*l2[j];
            zB = (zB > 0.f) ? zB : 0.2f*zB;
            pB += zB * wa[j];
        }
#pragma unroll
        for (int o=4;o>0;o>>=1){
            pA += __shfl_xor_sync(0xffffffffu, pA, o);
            pB += __shfl_xor_sync(0xffffffffu, pB, o);
        }
        float h0A = __shfl_sync(0xffffffffu, pA, 0),  h1A = __shfl_sync(0xffffffffu, pA, 8);
        float h2A = __shfl_sync(0xffffffffu, pA, 16), h3A = __shfl_sync(0xffffffffu, pA, 24);
        float h0B = __shfl_sync(0xffffffffu, pB, 0),  h1B = __shfl_sync(0xffffffffu, pB, 8);
        float h2B = __shfl_sync(0xffffffffu, pB, 16), h3B = __shfl_sync(0xffffffffu, pB, 24);

        float hvA = (lane==0)?h0A:(lane==1)?h1A:(lane==2)?h2A:h3A;
        float hvB = (lane==4)?h0B:(lane==5)?h1B:(lane==6)?h2B:h3B;
        if (lane < 4){
            if (i < CAPW) ((float*)&s_cache[w][i])[lane] = hvA;
            else          g_logits[(size_t)(st+i)*HH + lane] = hvA;
        } else if (lane < 8){
            if (i+1 < CAPW) ((float*)&s_cache[w][i+1])[lane-4] = hvB;
            else            g_logits[(size_t)(st+i+1)*HH + (lane-4)] = hvB;
        }
        m0 = fmaxf(m0, fmaxf(h0A,h0B)); m1 = fmaxf(m1, fmaxf(h1A,h1B));
        m2 = fmaxf(m2, fmaxf(h2A,h2B)); m3 = fmaxf(m3, fmaxf(h3A,h3B));
    }
    if (i < deg){
        int e = (i<CAPW) ? s_csr[w][i] : g_csr[st+i];
        int s = ei[e];
        float r0 = ea[(size_t)e*3+0], r1 = ea[(size_t)e*3+1], dd = ea[(size_t)e*3+2];
        const float4* xl4 = (const float4*)(g_xl + (size_t)s*CC);
        float4 a0 = xl4[lane*2], a1 = xl4[lane*2+1];
        float xs[8] = { a0.x+xr[0], a0.y+xr[1], a0.z+xr[2], a0.w+xr[3],
                        a1.x+xr[4], a1.y+xr[5], a1.z+xr[6], a1.w+xr[7] };
        float p = 0.f;
#pragma unroll
        for (int j=0;j<8;j++){
            float z = xs[j] + r0*l0[j] + r1*l1[j] + dd*l2[j];
            z = (z > 0.f) ? z : 0.2f*z;
            p += z * wa[j];
        }
#pragma unroll
        for (int o=4;o>0;o>>=1) p += __shfl_xor_sync(0xffffffffu, p, o);
        float h0 = __shfl_sync(0xffffffffu, p, 0),  h1 = __shfl_sync(0xffffffffu, p, 8);
        float h2 = __shfl_sync(0xffffffffu, p, 16), h3 = __shfl_sync(0xffffffffu, p, 24);
        if (lane < 4){
            float hv = (lane==0)?h0:(lane==1)?h1:(lane==2)?h2:h3;
            if (i < CAPW) ((float*)&s_cache[w][i])[lane] = hv;
            else          g_logits[(size_t)(st+i)*HH + lane] = hv;
        }
        m0 = fmaxf(m0, h0); m1 = fmaxf(m1, h1);
        m2 = fmaxf(m2, h2); m3 = fmaxf(m3, h3);
    }
    __syncwarp();

    // ---- pass 2: exp + sums ----
    float s0=0.f, s1=0.f, s2=0.f, s3=0.f;
    for (int k=lane; k<deg; k+=32){
        float4 lg = (k<CAPW) ? s_cache[w][k] : *(float4*)&g_logits[(size_t)(st+k)*HH];
        float4 ex;
        ex.x = __expf(lg.x - m0); ex.y = __expf(lg.y - m1);
        ex.z = __expf(lg.z - m2); ex.w = __expf(lg.w - m3);
        if (k<CAPW) s_cache[w][k] = ex;
        else *(float4*)&g_logits[(size_t)(st+k)*HH] = ex;
        s0 += ex.x; s1 += ex.y; s2 += ex.z; s3 += ex.w;
    }
    s0 = wsum(s0); s1 = wsum(s1); s2 = wsum(s2); s3 = wsum(s3);
    float i0 = 1.f/(s0+1e-16f), i1 = 1.f/(s1+1e-16f);
    float i2 = 1.f/(s2+1e-16f), i3 = 1.f/(s3+1e-16f);
    __syncwarp();

    for (int k=lane; k<deg; k+=32){
        float4 ex = (k<CAPW) ? s_cache[w][k] : *(float4*)&g_logits[(size_t)(st+k)*HH];
        float4 al = make_float4(ex.x*i0, ex.y*i1, ex.z*i2, ex.w*i3);
        if (k<CAPW) s_cache[w][k] = al;
        else *(float4*)&g_logits[(size_t)(st+k)*HH] = al;
        int e = (k<CAPW) ? s_csr[w][k] : g_csr[st+k];
        *(float4*)&alpha_out[(size_t)e*HH] = al;
    }
    __syncwarp();

    // ---- pass 3: aggregation (2 edges in flight) ----
    int hsel = lane >> 3;
    float acc[8] = {0.f,0.f,0.f,0.f,0.f,0.f,0.f,0.f};
    i = 0;
    for (; i+1 < deg; i += 2){
        int eA = (i   < CAPW) ? s_csr[w][i]   : g_csr[st+i];
        int eB = (i+1 < CAPW) ? s_csr[w][i+1] : g_csr[st+i+1];
        int sA = ei[eA], sB = ei[eB];
        float alA = (i   < CAPW) ? ((float*)&s_cache[w][i])[hsel]   : g_logits[(size_t)(st+i)*HH + hsel];
        float alB = (i+1 < CAPW) ? ((float*)&s_cache[w][i+1])[hsel] : g_logits[(size_t)(st+i+1)*HH + hsel];
        const float4* xlA = (const float4*)(g_xl + (size_t)sA*CC);
        const float4* xlB = (const float4*)(g_xl + (size_t)sB*CC);
        float4 a0A = xlA[lane*2], a1A = xlA[lane*2+1];
        float4 a0B = xlB[lane*2], a1B = xlB[lane*2+1];
        acc[0] += alA*a0A.x + alB*a0B.x; acc[1] += alA*a0A.y + alB*a0B.y;
        acc[2] += alA*a0A.z + alB*a0B.z; acc[3] += alA*a0A.w + alB*a0B.w;
        acc[4] += alA*a1A.x + alB*a1B.x; acc[5] += alA*a1A.y + alB*a1B.y;
        acc[6] += alA*a1A.z + alB*a1B.z; acc[7] += alA*a1A.w + alB*a1B.w;
    }
    if (i < deg){
        int e = (i<CAPW) ? s_csr[w][i] : g_csr[st+i];
        int s = ei[e];
        float al = (i<CAPW) ? ((float*)&s_cache[w][i])[hsel] : g_logits[(size_t)(st+i)*HH + hsel];
        const float4* xl4 = (const float4*)(g_xl + (size_t)s*CC);
        float4 a0 = xl4[lane*2], a1 = xl4[lane*2+1];
        acc[0] += al*a0.x; acc[1] += al*a0.y; acc[2] += al*a0.z; acc[3] += al*a0.w;
        acc[4] += al*a1.x; acc[5] += al*a1.y; acc[6] += al*a1.z; acc[7] += al*a1.w;
    }

    // ---- epilogue: LN + residual + SiLU ----
    float v[8], part = 0.f;
#pragma unroll
    for (int j=0;j<8;j++){ v[j] = acc[j] + convb[cbase+j]; part += v[j]; }
    float mean = wsum(part) * (1.f/256.f);
    float vp = 0.f;
#pragma unroll
    for (int j=0;j<8;j++){ v[j] -= mean; vp += v[j]*v[j]; }
    float var = wsum(vp) * (1.f/256.f);
    float rs = rsqrtf(var + 1e-5f);

    const float4* id4 = (const float4*)(g_ident + (size_t)n*CC);
    float4 d0 = id4[lane*2], d1 = id4[lane*2+1];
    float idv[8] = { d0.x,d0.y,d0.z,d0.w, d1.x,d1.y,d1.z,d1.w };
    float o[8];
#pragma unroll
    for (int j=0;j<8;j++){
        int c = cbase+j;
        float ov = v[j]*rs*ng[c] + nb[c];
        float tt = ov + idv[j];
        o[j] = rtf32(tt / (1.f + __expf(-tt)));   // pre-round for proj GEMM
    }
    float4* pr4 = (float4*)(g_pre + (size_t)n*CC);
    pr4[lane*2]   = make_float4(o[0],o[1],o[2],o[3]);
    pr4[lane*2+1] = make_float4(o[4],o[5],o[6],o[7]);
}

// ---------------- launch ----------------
extern "C" void kernel_launch(void* const* d_in, const int* in_sizes, int n_in,
                              void* d_out, int out_size)
{
    const float* x        = (const float*)d_in[0];
    const float* kpts     = (const float*)d_in[1];
    const float* pts3d    = (const float*)d_in[2];
    const float* pe_w1    = (const float*)d_in[3];
    const float* pe_b1    = (const float*)d_in[4];
    const float* pe_g1    = (const float*)d_in[5];
    const float* pe_bn1   = (const float*)d_in[6];
    const float* pe_w2    = (const float*)d_in[7];
    const float* pe_b2    = (const float*)d_in[8];
    const float* pe_g2    = (const float*)d_in[9];
    const float* pe_bn2   = (const float*)d_in[10];
    const float* lin_l_w  = (const float*)d_in[11];
    const float* lin_l_b  = (const float*)d_in[12];
    const float* lin_r_w  = (const float*)d_in[13];
    const float* lin_r_b  = (const float*)d_in[14];
    const float* lin_edge = (const float*)d_in[15];
    const float* att      = (const float*)d_in[16];
    const float* conv_b   = (const float*)d_in[17];
    const float* norm_g   = (const float*)d_in[18];
    const float* norm_b   = (const float*)d_in[19];
    const float* res_w    = (const float*)d_in[20];
    const float* res_b    = (const float*)d_in[21];
    const float* proj_w   = (const float*)d_in[22];
    const float* proj_b   = (const float*)d_in[23];
    const int*   ei       = (const int*)d_in[24];

    float* out       = (float*)d_out;
    float* alpha_out = out + (size_t)NN*CC;          // [E,4]
    float* ea_out    = alpha_out + (size_t)EE*HH;    // [E,3]

    float *p_xcomb, *p_xl, *p_xr, *p_ident, *p_pre, *p_wr;
    cudaGetSymbolAddress((void**)&p_xcomb, g_xcomb);
    cudaGetSymbolAddress((void**)&p_xl,    g_xl);
    cudaGetSymbolAddress((void**)&p_xr,    g_xr);
    cudaGetSymbolAddress((void**)&p_ident, g_ident);
    cudaGetSymbolAddress((void**)&p_pre,   g_pre);
    cudaGetSymbolAddress((void**)&p_wr,    g_wr);

    cudaFuncSetAttribute(k_tcgemm2, cudaFuncAttributeMaxDynamicSharedMemorySize, GEMM_SMEM);

    k_init<<<64, 256>>>();
    k_prep<<<1, 256>>>(pe_w2);
    k_roundw<<<(CC*CC + 255)/256, 256>>>(lin_l_w, lin_r_w, res_w, proj_w);
    k_pos<<<(NN + 7)/8, 256>>>(x, kpts, pts3d,
                               pe_w1, pe_b1, pe_g1, pe_bn1,
                               pe_b2, pe_g2, pe_bn2);

    // fused lin_l + lin_r + res GEMMs (tf32, 128x128 tiles, cp.async pipelined)
    dim3 g3((NN + 127)/128, 6);
    k_tcgemm2<<<g3, 256, GEMM_SMEM>>>(p_xcomb, p_wr, 0,
                                      lin_l_b, lin_r_b, res_b,
                                      p_xl, p_xr, p_ident, NN);

    k_edgeattr<<<(EE + 255)/256, 256>>>(ei, ea_out);
    k_scan<<<1, 1024>>>();
    k_scatter<<<(EE + 255)/256, 256>>>(ei);

    // fused edge phase
    k_wnode<<<(NN + 7)/8, 256>>>(ei, ea_out, lin_edge, att,
                                 conv_b, norm_g, norm_b, alpha_out);

    // projector GEMM
    dim3 g1((NN + 127)/128, 2);
    k_tcgemm2<<<g1, 256, GEMM_SMEM>>>(p_pre, p_wr, 3,
                                      proj_b, proj_b, proj_b,
                                      out, out, out, NN);
}

// round 11
// speedup vs baseline: 2.1564x; 1.0339x over previous
#include <cuda_runtime.h>
#include <cuda_bf16.h>
#include <mma.h>
#include <math.h>
#include <cstdint>

using namespace nvcuda;

// Problem constants
#define NN 50000
#define EE 800000
#define HH 4
#define FF 64
#define CC 256   // H*F == CIN
#define CAPW 64  // per-warp cached degree; fallback to global beyond

// ---------------- device scratch (static, no allocation) ----------------
__device__ float    g_xcomb [(size_t)NN*CC];
__device__ float    g_xl    [(size_t)NN*CC];
__device__ float    g_xr    [(size_t)NN*CC];
__device__ float    g_ident [(size_t)NN*CC];
__device__ float    g_pre   [(size_t)NN*CC];
__device__ float    g_logits[(size_t)EE*HH];   // high-degree fallback (CSR-slot indexed)
__device__ float    g_nuv   [(size_t)NN*2];
__device__ float    g_w2t   [32*64];           // transposed pe_w2
__device__ float    g_wr    [4*CC*CC];         // tf32-rounded weights: lin_l, lin_r, res, proj
__device__ int      g_deg   [NN+1];
__device__ int      g_off   [NN+1];
__device__ int      g_cursor[NN+1];
__device__ int      g_csr   [EE];

// ---------------- helpers ----------------
__device__ __forceinline__ float wsum(float v){
#pragma unroll
    for (int o=16;o>0;o>>=1) v += __shfl_xor_sync(0xffffffffu, v, o);
    return v;
}

__device__ __forceinline__ float rtf32(float x){
    return wmma::__float_to_tf32(x);
}

__device__ __forceinline__ void cp_async16(unsigned int dst, const float* src, bool full){
    if (full)
        asm volatile("cp.async.cg.shared.global [%0], [%1], 16;" :: "r"(dst), "l"(src));
    else
        asm volatile("cp.async.cg.shared.global [%0], [%1], 16, 0;" :: "r"(dst), "l"(src));
}

// ---------------- kernels ----------------
__global__ void k_init(){
    int i = blockIdx.x*blockDim.x + threadIdx.x;
    int stride = gridDim.x*blockDim.x;
    for (int j=i; j<NN+1; j+=stride) g_deg[j]=0;
}

// transpose pe_w2 (64x32 -> 32x64) for coalesced reads in k_pos
__global__ void k_prep(const float* __restrict__ w2){
    for (int idx=threadIdx.x; idx<2048; idx+=blockDim.x){
        int k = idx >> 6, c = idx & 63;
        g_w2t[idx] = w2[c*32 + k];
    }
}

// round the 4 GEMM weight matrices to tf32 once
__global__ void k_roundw(const float* __restrict__ w0, const float* __restrict__ w1,
                         const float* __restrict__ w2, const float* __restrict__ w3){
    int i = blockIdx.x*blockDim.x + threadIdx.x;
    if (i >= CC*CC) return;
    g_wr[i]           = rtf32(w0[i]);
    g_wr[CC*CC + i]   = rtf32(w1[i]);
    g_wr[2*CC*CC + i] = rtf32(w2[i]);
    g_wr[3*CC*CC + i] = rtf32(w3[i]);
}

// positional encoder + build x_comb (tf32-rounded). One warp per node.
__global__ void k_pos(const float* __restrict__ x, const float* __restrict__ kpts,
                      const float* __restrict__ pts,
                      const float* __restrict__ w1, const float* __restrict__ b1,
                      const float* __restrict__ g1, const float* __restrict__ bn1,
                      const float* __restrict__ b2,
                      const float* __restrict__ g2, const float* __restrict__ bn2)
{
    int node = (blockIdx.x*blockDim.x + threadIdx.x) >> 5;
    int lane = threadIdx.x & 31;
    if (node >= NN) return;
    float u  = kpts[node*2+0] * (1.f/1216.f);
    float v  = kpts[node*2+1] * (1.f/352.f);
    float dep = fminf(fmaxf(pts[node*3+2], 0.1f), 100.f);
    if (lane == 0){ g_nuv[node*2]=u; g_nuv[node*2+1]=v; }

    float a = w1[lane*3+0]*u + w1[lane*3+1]*v + w1[lane*3+2]*dep + b1[lane];
    float m = wsum(a) * (1.f/32.f);
    float d0 = a - m;
    float var = wsum(d0*d0) * (1.f/32.f);
    float hn = d0 * rsqrtf(var + 1e-5f) * g1[lane] + bn1[lane];
    float h = hn / (1.f + expf(-hn));

    float acc0 = b2[lane], acc1 = b2[lane+32];
#pragma unroll
    for (int k=0;k<32;k++){
        float hk = __shfl_sync(0xffffffffu, h, k);
        acc0 += hk * g_w2t[k*64 + lane];
        acc1 += hk * g_w2t[k*64 + 32 + lane];
    }
    float m2 = wsum(acc0 + acc1) * (1.f/64.f);
    float e0 = acc0 - m2, e1 = acc1 - m2;
    float var2 = wsum(e0*e0 + e1*e1) * (1.f/64.f);
    float rs = rsqrtf(var2 + 1e-5f);
    float p0 = e0*rs*g2[lane]    + bn2[lane];
    float p1 = e1*rs*g2[lane+32] + bn2[lane+32];

    size_t base = (size_t)node * CC;
    g_xcomb[base + 192 + lane] = rtf32(p0);
    g_xcomb[base + 224 + lane] = rtf32(p1);
#pragma unroll
    for (int j=lane; j<192; j+=32) g_xcomb[base + j] = rtf32(x[(size_t)node*192 + j]);
}

// ---------------- tf32 tensor-core GEMM, 128x128 tile, cp.async 2-stage ----------------
#define SS (128*40)                 // floats per matrix per stage
#define GEMM_SMEM (2*2*SS*4)        // 81920 B (also covers Cs 128*136*4 = 69632)

__global__ void __launch_bounds__(256, 2)
k_tcgemm2(const float* __restrict__ A,
          const float* __restrict__ Wbase, int tgt0,
          const float* __restrict__ b0, const float* __restrict__ b1,
          const float* __restrict__ b2,
          float* __restrict__ C0, float* __restrict__ C1,
          float* __restrict__ C2, int M)
{
    extern __shared__ float sm[];

    int t  = threadIdx.x;
    int m0 = blockIdx.x * 128;
    int tgt = blockIdx.y >> 1;
    int c0  = (blockIdx.y & 1) * 128;

    const float* W    = Wbase + (size_t)(tgt0 + tgt)*CC*CC;
    const float* bias = (tgt == 0) ? b0 : (tgt == 1) ? b1 : b2;
    float*       C    = (tgt == 0) ? C0 : (tgt == 1) ? C1 : C2;

    int warp = t >> 5;
    int r  = (warp & 3) * 32;
    int cb = (warp >> 2) * 64;

    unsigned int smb = (unsigned int)__cvta_generic_to_shared(sm);

    int rows[4], cols[4];
#pragma unroll
    for (int j=0;j<4;j++){
        int id = t + j*256;
        rows[j] = id >> 3;
        cols[j] = (id & 7) * 4;
    }

    wmma::fragment<wmma::accumulator, 16, 16, 8, float> acc[2][4];
#pragma unroll
    for (int i=0;i<2;i++)
#pragma unroll
        for (int j=0;j<4;j++) wmma::fill_fragment(acc[i][j], 0.f);

    auto issue = [&](int k0, int s){
#pragma unroll
        for (int j=0;j<4;j++){
            int row = rows[j], col = cols[j];
            bool vA = (m0 + row < M);
            const float* srcA = &A[(size_t)((vA ? m0 + row : 0)) * CC + k0 + col];
            cp_async16(smb + (unsigned int)((s*2*SS + row*40 + col)*4), srcA, vA);
            const float* srcW = &W[(size_t)(c0 + row) * CC + k0 + col];
            cp_async16(smb + (unsigned int)((s*2*SS + SS + row*40 + col)*4), srcW, true);
        }
        asm volatile("cp.async.commit_group;" ::: "memory");
    };

    issue(0, 0);

    for (int it = 0; it < 8; ++it){
        int s = it & 1;
        if (it < 7) issue((it+1)*32, s^1);
        if (it < 7) asm volatile("cp.async.wait_group 1;" ::: "memory");
        else        asm volatile("cp.async.wait_group 0;" ::: "memory");
        __syncthreads();

        float* As = sm + s*2*SS;
        float* Ws = As + SS;
#pragma unroll
        for (int kk = 0; kk < 32; kk += 8){
            wmma::fragment<wmma::matrix_a, 16, 16, 8, wmma::precision::tf32, wmma::row_major> af[2];
            wmma::fragment<wmma::matrix_b, 16, 16, 8, wmma::precision::tf32, wmma::col_major> bf[4];
#pragma unroll
            for (int i = 0; i < 2; i++)
                wmma::load_matrix_sync(af[i], &As[(r + 16*i)*40 + kk], 40);
#pragma unroll
            for (int j = 0; j < 4; j++)
                wmma::load_matrix_sync(bf[j], &Ws[(cb + 16*j)*40 + kk], 40);
#pragma unroll
            for (int i = 0; i < 2; i++)
#pragma unroll
                for (int j = 0; j < 4; j++)
                    wmma::mma_sync(acc[i][j], af[i], bf[j], acc[i][j]);
        }
        __syncthreads();
    }

    float* Cs = sm;  // [128][136] aliases both stages
#pragma unroll
    for (int i = 0; i < 2; i++)
#pragma unroll
        for (int j = 0; j < 4; j++)
            wmma::store_matrix_sync(&Cs[(r + 16*i)*136 + cb + 16*j], acc[i][j], 136, wmma::mem_row_major);
    __syncthreads();

    int col4 = (t & 31) * 4;
    int rb   = t >> 5;
    float4 bv = *(const float4*)&bias[c0 + col4];
#pragma unroll
    for (int i = 0; i < 16; i++){
        int row = rb + i * 8;
        int m = m0 + row;
        if (m < M){
            float4 v = *(float4*)&Cs[row*136 + col4];
            v.x += bv.x; v.y += bv.y; v.z += bv.z; v.w += bv.w;
            *(float4*)&C[(size_t)m * CC + c0 + col4] = v;
        }
    }
}

// edge_attr output + degree histogram
__global__ void k_edgeattr(const int* __restrict__ ei, float* __restrict__ ea)
{
    int e = blockIdx.x*blockDim.x + threadIdx.x;
    if (e >= EE) return;
    int s = ei[e], d = ei[EE + e];
    float r0 = g_nuv[d*2+0] - g_nuv[s*2+0];
    float r1 = g_nuv[d*2+1] - g_nuv[s*2+1];
    float dist = sqrtf(r0*r0 + r1*r1);
    ea[(size_t)e*3+0] = r0;
    ea[(size_t)e*3+1] = r1;
    ea[(size_t)e*3+2] = dist;
    atomicAdd(&g_deg[d], 1);
}

// single-block exclusive scan of degrees -> offsets (+cursor copy)
__global__ void k_scan()
{
    __shared__ int warpsum[32];
    __shared__ int warpoff[32];
    int t = threadIdx.x;
    int lane = t & 31, wid = t >> 5;
    int carry = 0;
    for (int base = 0; base < NN; base += 1024){
        int v = (base + t < NN) ? g_deg[base + t] : 0;
        int s = v;
#pragma unroll
        for (int o = 1; o < 32; o <<= 1){
            int n = __shfl_up_sync(0xffffffffu, s, o);
            if (lane >= o) s += n;
        }
        if (lane == 31) warpsum[wid] = s;
        __syncthreads();
        if (wid == 0){
            int ws = warpsum[lane];
            int t2 = ws;
#pragma unroll
            for (int o = 1; o < 32; o <<= 1){
                int n = __shfl_up_sync(0xffffffffu, t2, o);
                if (lane >= o) t2 += n;
            }
            warpoff[lane] = t2 - ws;
            if (lane == 31) warpsum[0] = t2;
        }
        __syncthreads();
        int tile_total = warpsum[0];
        if (base + t < NN){
            int ex = carry + warpoff[wid] + s - v;
            g_off[base + t] = ex;
            g_cursor[base + t] = ex;
        }
        __syncthreads();
        carry += tile_total;
    }
    if (t == 0) g_off[NN] = carry;
}

__global__ void k_scatter(const int* __restrict__ ei)
{
    int e = blockIdx.x*blockDim.x + threadIdx.x;
    if (e >= EE) return;
    int d = ei[EE + e];
    int pos = atomicAdd(&g_cursor[d], 1);
    g_csr[pos] = e;
}

// ---------------- warp-per-node fused attention, ONLINE SOFTMAX ----------------
// Single xl-gather pass: running max + rescaled accumulator (flash-attention style).
// Logits cached only for alpha output.
__global__ void __launch_bounds__(256)
k_wnode(const int* __restrict__ ei, const float* __restrict__ ea,
        const float* __restrict__ lew, const float* __restrict__ att,
        const float* __restrict__ convb, const float* __restrict__ ng,
        const float* __restrict__ nb, float* __restrict__ alpha_out)
{
    __shared__ float4 s_cache[8][CAPW];   // logits per edge (4 heads)
    __shared__ int    s_csr  [8][CAPW];

    int w = threadIdx.x >> 5, lane = threadIdx.x & 31;
    int n = blockIdx.x*8 + w;
    if (n >= NN) return;

    int st = g_off[n];
    int deg = g_off[n+1] - st;
    int cbase = lane*8;
    int hsel = lane >> 3;

    float wa[8], l0[8], l1[8], l2[8];
#pragma unroll
    for (int j=0;j<8;j++){
        int c = cbase+j;
        wa[j] = att[c];
        l0[j] = lew[c*3+0]; l1[j] = lew[c*3+1]; l2[j] = lew[c*3+2];
    }
    float xr[8];
    {
        const float4* xr4 = (const float4*)(g_xr + (size_t)n*CC);
        float4 t0 = xr4[lane*2], t1 = xr4[lane*2+1];
        xr[0]=t0.x; xr[1]=t0.y; xr[2]=t0.z; xr[3]=t0.w;
        xr[4]=t1.x; xr[5]=t1.y; xr[6]=t1.z; xr[7]=t1.w;
    }

    for (int i=lane; i<deg && i<CAPW; i+=32) s_csr[w][i] = g_csr[st+i];
    __syncwarp();

    // online-softmax state: per-lane for OWN head (identical across the 8 lanes of a head)
    float mh = -INFINITY;     // running max
    float sh = 0.f;           // running sum of exp
    float acc[8] = {0.f,0.f,0.f,0.f,0.f,0.f,0.f,0.f};   // rescaled weighted xl accumulator

    // ---- single pass: logits + online softmax aggregation (2 edges in flight) ----
    int i = 0;
    for (; i+1 < deg; i += 2){
        int eA = (i   < CAPW) ? s_csr[w][i]   : g_csr[st+i];
        int eB = (i+1 < CAPW) ? s_csr[w][i+1] : g_csr[st+i+1];
        int sA = ei[eA], sB = ei[eB];
        float r0A = ea[(size_t)eA*3+0], r1A = ea[(size_t)eA*3+1], ddA = ea[(size_t)eA*3+2];
        float r0B = ea[(size_t)eB*3+0], r1B = ea[(size_t)eB*3+1], ddB = ea[(size_t)eB*3+2];
        const float4* xlA = (const float4*)(g_xl + (size_t)sA*CC);
        const float4* xlB = (const float4*)(g_xl + (size_t)sB*CC);
        float4 a0A = xlA[lane*2], a1A = xlA[lane*2+1];
        float4 a0B = xlB[lane*2], a1B = xlB[lane*2+1];
        float xA[8] = { a0A.x,a0A.y,a0A.z,a0A.w, a1A.x,a1A.y,a1A.z,a1A.w };
        float xB[8] = { a0B.x,a0B.y,a0B.z,a0B.w, a1B.x,a1B.y,a1B.z,a1B.w };

        float pA = 0.f, pB = 0.f;
#pragma unroll
        for (int j=0;j<8;j++){
            float zA = xA[j] + xr[j] + r0A*l0[j] + r1A*l1[j] + ddA*l2[j];
            zA = (zA > 0.f) ? zA : 0.2f*zA;
            pA += zA * wa[j];
            float zB = xB[j] + xr[j] + r0B*l0[j] + r1B*l1[j] + ddB*l2[j];
            zB = (zB > 0.f) ? zB : 0.2f*zB;
            pB += zB * wa[j];
        }
#pragma unroll
        for (int o=4;o>0;o>>=1){
            pA += __shfl_xor_sync(0xffffffffu, pA, o);
            pB += __shfl_xor_sync(0xffffffffu, pB, o);
        }
        // per-head logits available at lanes {0,8,16,24}
        float hA = __shfl_sync(0xffffffffu, pA, hsel << 3);   // own head's logit, edge A
        float hB = __shfl_sync(0xffffffffu, pB, hsel << 3);
        // cache logits for alpha output
        {
            float h0A = __shfl_sync(0xffffffffu, pA, 0),  h1A = __shfl_sync(0xffffffffu, pA, 8);
            float h2A = __shfl_sync(0xffffffffu, pA, 16), h3A = __shfl_sync(0xffffffffu, pA, 24);
            float h0B = __shfl_sync(0xffffffffu, pB, 0),  h1B = __shfl_sync(0xffffffffu, pB, 8);
            float h2B = __shfl_sync(0xffffffffu, pB, 16), h3B = __shfl_sync(0xffffffffu, pB, 24);
            if (lane < 4){
                float hv = (lane==0)?h0A:(lane==1)?h1A:(lane==2)?h2A:h3A;
                if (i < CAPW) ((float*)&s_cache[w][i])[lane] = hv;
                else          g_logits[(size_t)(st+i)*HH + lane] = hv;
            } else if (lane < 8){
                float hv = (lane==4)?h0B:(lane==5)?h1B:(lane==6)?h2B:h3B;
                if (i+1 < CAPW) ((float*)&s_cache[w][i+1])[lane-4] = hv;
                else            g_logits[(size_t)(st+i+1)*HH + (lane-4)] = hv;
            }
        }
        // online update
        float mnew = fmaxf(mh, fmaxf(hA, hB));
        float scale = __expf(mh - mnew);
        float wAx = __expf(hA - mnew);
        float wBx = __expf(hB - mnew);
        sh = sh*scale + wAx + wBx;
#pragma unroll
        for (int j=0;j<8;j++)
            acc[j] = acc[j]*scale + wAx*xA[j] + wBx*xB[j];
        mh = mnew;
    }
    if (i < deg){
        int e = (i<CAPW) ? s_csr[w][i] : g_csr[st+i];
        int s = ei[e];
        float r0 = ea[(size_t)e*3+0], r1 = ea[(size_t)e*3+1], dd = ea[(size_t)e*3+2];
        const float4* xl4 = (const float4*)(g_xl + (size_t)s*CC);
        float4 a0 = xl4[lane*2], a1 = xl4[lane*2+1];
        float xA[8] = { a0.x,a0.y,a0.z,a0.w, a1.x,a1.y,a1.z,a1.w };
        float p = 0.f;
#pragma unroll
        for (int j=0;j<8;j++){
            float z = xA[j] + xr[j] + r0*l0[j] + r1*l1[j] + dd*l2[j];
            z = (z > 0.f) ? z : 0.2f*z;
            p += z * wa[j];
        }
#pragma unroll
        for (int o=4;o>0;o>>=1) p += __shfl_xor_sync(0xffffffffu, p, o);
        float hA = __shfl_sync(0xffffffffu, p, hsel << 3);
        {
            float h0 = __shfl_sync(0xffffffffu, p, 0),  h1 = __shfl_sync(0xffffffffu, p, 8);
            float h2 = __shfl_sync(0xffffffffu, p, 16), h3 = __shfl_sync(0xffffffffu, p, 24);
            if (lane < 4){
                float hv = (lane==0)?h0:(lane==1)?h1:(lane==2)?h2:h3;
                if (i < CAPW) ((float*)&s_cache[w][i])[lane] = hv;
                else          g_logits[(size_t)(st+i)*HH + lane] = hv;
            }
        }
        float mnew = fmaxf(mh, hA);
        float scale = __expf(mh - mnew);
        float wAx = __expf(hA - mnew);
        sh = sh*scale + wAx;
#pragma unroll
        for (int j=0;j<8;j++)
            acc[j] = acc[j]*scale + wAx*xA[j];
        mh = mnew;
    }
    __syncwarp();

    // broadcast per-head final (m, s) to all lanes
    float fm0 = __shfl_sync(0xffffffffu, mh, 0),  fs0 = __shfl_sync(0xffffffffu, sh, 0);
    float fm1 = __shfl_sync(0xffffffffu, mh, 8),  fs1 = __shfl_sync(0xffffffffu, sh, 8);
    float fm2 = __shfl_sync(0xffffffffu, mh, 16), fs2 = __shfl_sync(0xffffffffu, sh, 16);
    float fm3 = __shfl_sync(0xffffffffu, mh, 24), fs3 = __shfl_sync(0xffffffffu, sh, 24);
    float is0 = 1.f/(fs0+1e-16f), is1 = 1.f/(fs1+1e-16f);
    float is2 = 1.f/(fs2+1e-16f), is3 = 1.f/(fs3+1e-16f);

    // ---- alpha output pass (strided; logits from cache) ----
    for (int k=lane; k<deg; k+=32){
        float4 lg = (k<CAPW) ? s_cache[w][k] : *(float4*)&g_logits[(size_t)(st+k)*HH];
        float4 al;
        al.x = __expf(lg.x - fm0)*is0; al.y = __expf(lg.y - fm1)*is1;
        al.z = __expf(lg.z - fm2)*is2; al.w = __expf(lg.w - fm3)*is3;
        int e = (k<CAPW) ? s_csr[w][k] : g_csr[st+k];
        *(float4*)&alpha_out[(size_t)e*HH] = al;
    }

    // ---- epilogue: LN + residual + SiLU ----
    float inv = (hsel==0)?is0:(hsel==1)?is1:(hsel==2)?is2:is3;
    float v[8], part = 0.f;
#pragma unroll
    for (int j=0;j<8;j++){ v[j] = acc[j]*inv + convb[cbase+j]; part += v[j]; }
    float mean = wsum(part) * (1.f/256.f);
    float vp = 0.f;
#pragma unroll
    for (int j=0;j<8;j++){ v[j] -= mean; vp += v[j]*v[j]; }
    float var = wsum(vp) * (1.f/256.f);
    float rs = rsqrtf(var + 1e-5f);

    const float4* id4 = (const float4*)(g_ident + (size_t)n*CC);
    float4 d0 = id4[lane*2], d1 = id4[lane*2+1];
    float idv[8] = { d0.x,d0.y,d0.z,d0.w, d1.x,d1.y,d1.z,d1.w };
    float o[8];
#pragma unroll
    for (int j=0;j<8;j++){
        int c = cbase+j;
        float ov = v[j]*rs*ng[c] + nb[c];
        float tt = ov + idv[j];
        o[j] = rtf32(tt / (1.f + __expf(-tt)));   // pre-round for proj GEMM
    }
    float4* pr4 = (float4*)(g_pre + (size_t)n*CC);
    pr4[lane*2]   = make_float4(o[0],o[1],o[2],o[3]);
    pr4[lane*2+1] = make_float4(o[4],o[5],o[6],o[7]);
}

// ---------------- launch ----------------
extern "C" void kernel_launch(void* const* d_in, const int* in_sizes, int n_in,
                              void* d_out, int out_size)
{
    const float* x        = (const float*)d_in[0];
    const float* kpts     = (const float*)d_in[1];
    const float* pts3d    = (const float*)d_in[2];
    const float* pe_w1    = (const float*)d_in[3];
    const float* pe_b1    = (const float*)d_in[4];
    const float* pe_g1    = (const float*)d_in[5];
    const float* pe_bn1   = (const float*)d_in[6];
    const float* pe_w2    = (const float*)d_in[7];
    const float* pe_b2    = (const float*)d_in[8];
    const float* pe_g2    = (const float*)d_in[9];
    const float* pe_bn2   = (const float*)d_in[10];
    const float* lin_l_w  = (const float*)d_in[11];
    const float* lin_l_b  = (const float*)d_in[12];
    const float* lin_r_w  = (const float*)d_in[13];
    const float* lin_r_b  = (const float*)d_in[14];
    const float* lin_edge = (const float*)d_in[15];
    const float* att      = (const float*)d_in[16];
    const float* conv_b   = (const float*)d_in[17];
    const float* norm_g   = (const float*)d_in[18];
    const float* norm_b   = (const float*)d_in[19];
    const float* res_w    = (const float*)d_in[20];
    const float* res_b    = (const float*)d_in[21];
    const float* proj_w   = (const float*)d_in[22];
    const float* proj_b   = (const float*)d_in[23];
    const int*   ei       = (const int*)d_in[24];

    float* out       = (float*)d_out;
    float* alpha_out = out + (size_t)NN*CC;          // [E,4]
    float* ea_out    = alpha_out + (size_t)EE*HH;    // [E,3]

    float *p_xcomb, *p_xl, *p_xr, *p_ident, *p_pre, *p_wr;
    cudaGetSymbolAddress((void**)&p_xcomb, g_xcomb);
    cudaGetSymbolAddress((void**)&p_xl,    g_xl);
    cudaGetSymbolAddress((void**)&p_xr,    g_xr);
    cudaGetSymbolAddress((void**)&p_ident, g_ident);
    cudaGetSymbolAddress((void**)&p_pre,   g_pre);
    cudaGetSymbolAddress((void**)&p_wr,    g_wr);

    cudaFuncSetAttribute(k_tcgemm2, cudaFuncAttributeMaxDynamicSharedMemorySize, GEMM_SMEM);

    k_init<<<64, 256>>>();
    k_prep<<<1, 256>>>(pe_w2);
    k_roundw<<<(CC*CC + 255)/256, 256>>>(lin_l_w, lin_r_w, res_w, proj_w);
    k_pos<<<(NN + 7)/8, 256>>>(x, kpts, pts3d,
                               pe_w1, pe_b1, pe_g1, pe_bn1,
                               pe_b2, pe_g2, pe_bn2);

    // fused lin_l + lin_r + res GEMMs (tf32, 128x128 tiles, cp.async pipelined)
    dim3 g3((NN + 127)/128, 6);
    k_tcgemm2<<<g3, 256, GEMM_SMEM>>>(p_xcomb, p_wr, 0,
                                      lin_l_b, lin_r_b, res_b,
                                      p_xl, p_xr, p_ident, NN);

    k_edgeattr<<<(EE + 255)/256, 256>>>(ei, ea_out);
    k_scan<<<1, 1024>>>();
    k_scatter<<<(EE + 255)/256, 256>>>(ei);

    // fused edge phase (online softmax, single xl-gather pass)
    k_wnode<<<(NN + 7)/8, 256>>>(ei, ea_out, lin_edge, att,
                                 conv_b, norm_g, norm_b, alpha_out);

    // projector GEMM
    dim3 g1((NN + 127)/128, 2);
    k_tcgemm2<<<g1, 256, GEMM_SMEM>>>(p_pre, p_wr, 3,
                                      proj_b, proj_b, proj_b,
                                      out, out, out, NN);
}